// round 6
// baseline (speedup 1.0000x reference)
#include <cuda_runtime.h>
#include <cuda_fp16.h>
#include <math.h>
#include <stdint.h>

#define BB 4
#define NN_ 1024
#define DIM 256
#define HEADS 4
#define DH 64
#define DEPTH 4
#define MLP 1024
#define EPS 1e-5f
#define SCALE 0.0625f   // DIM^-0.5

// ---------------- scratch ----------------
__device__ float g_x  [BB*NN_*DIM];
__device__ float g_xn [BB*NN_*DIM];
__device__ float g_xma[BB*NN_*DIM];
__device__ float g_q  [BB*NN_*DIM];
__device__ float g_kv [BB*NN_*2*DIM];
__device__ float g_ao [BB*NN_*DIM];
__device__ float g_G  [(long)BB*NN_*NN_];
__device__ __half g_bias[(long)BB*HEADS*NN_*NN_];
__device__ float g_ff [BB*NN_*MLP];
__device__ float g_opart[(long)2*BB*HEADS*NN_*DH];   // split-KV partial O (unnormalized)
__device__ float2 g_mlp[2*BB*HEADS*NN_];             // split-KV partial (m, l)

// ---------------- helpers ----------------
__device__ __forceinline__ float warp_sum(float v) {
#pragma unroll
    for (int o = 16; o; o >>= 1) v += __shfl_xor_sync(0xffffffffu, v, o);
    return v;
}
__device__ __forceinline__ float warp_max(float v) {
#pragma unroll
    for (int o = 16; o; o >>= 1) v = fmaxf(v, __shfl_xor_sync(0xffffffffu, v, o));
    return v;
}
__device__ __forceinline__ float block_sum(float v, float* sh) {
    int lane = threadIdx.x & 31, w = threadIdx.x >> 5;
    v = warp_sum(v);
    if (lane == 0) sh[w] = v;
    __syncthreads();
    v = (lane < 8) ? sh[lane] : 0.0f;
    v = warp_sum(v);
    __syncthreads();
    return v;
}
__device__ __forceinline__ float block_max(float v, float* sh) {
    int lane = threadIdx.x & 31, w = threadIdx.x >> 5;
    v = warp_max(v);
    if (lane == 0) sh[w] = v;
    __syncthreads();
    v = (lane < 8) ? sh[lane] : -INFINITY;
    v = warp_max(v);
    __syncthreads();
    return v;
}

__device__ __forceinline__ uint32_t f2tf(float f) {
    uint32_t u;
    asm("cvt.rna.tf32.f32 %0, %1;" : "=r"(u) : "f"(f));
    return u;
}
__device__ __forceinline__ uint32_t tfb(uint32_t bits) {
    return f2tf(__uint_as_float(bits));
}
__device__ __forceinline__ void mma_tf32(float c[4], const uint32_t a[4], const uint32_t b[2]) {
    asm volatile(
        "mma.sync.aligned.m16n8k8.row.col.f32.tf32.tf32.f32 "
        "{%0,%1,%2,%3}, {%4,%5,%6,%7}, {%8,%9}, {%0,%1,%2,%3};"
        : "+f"(c[0]), "+f"(c[1]), "+f"(c[2]), "+f"(c[3])
        : "r"(a[0]), "r"(a[1]), "r"(a[2]), "r"(a[3]), "r"(b[0]), "r"(b[1]));
}
__device__ __forceinline__ uint4 cvt4(float4 v) {
    return make_uint4(f2tf(v.x), f2tf(v.y), f2tf(v.z), f2tf(v.w));
}
__device__ __forceinline__ uint32_t smem_u32(const void* p) {
    return (uint32_t)__cvta_generic_to_shared(p);
}
__device__ __forceinline__ void cpa16(uint32_t dst, const void* src) {
    asm volatile("cp.async.cg.shared.global [%0], [%1], 16;" :: "r"(dst), "l"(src));
}
__device__ __forceinline__ void cp_commit() { asm volatile("cp.async.commit_group;"); }
template <int N> __device__ __forceinline__ void cp_wait() {
    asm volatile("cp.async.wait_group %0;" :: "n"(N));
}

// ---------------- dense GEMM core: BMx64, BK=32, 2-stage ----------------
// BM=128: warps 4x2 (32x32). BM=64: warps 2x4 (32x16) -> 2x blocks for small GEMMs.
#define LDA 36
#define LDB 72

template <int EPI, int BM>
__device__ __forceinline__ void gemm_core(
    const float* __restrict__ A, const float* __restrict__ Bm,
    float* __restrict__ C, const float* __restrict__ E, const float* __restrict__ bv,
    int K, int lda, int ldb, int ldc, int row0, int col0, uint32_t* smraw) {
    constexpr int WARPS_N = (BM == 128) ? 2 : 4;
    constexpr int WN = 64 / WARPS_N;          // 32 or 16
    constexpr int NT = WN / 8;                // 4 or 2
    constexpr int AW = BM / 32;               // cp.async per thread (A)
    uint32_t* As = smraw;
    uint32_t* Bs = smraw + 2 * BM * LDA;

    const int tid = threadIdx.x, wid = tid >> 5, lane = tid & 31;
    const int gid = lane >> 2, tg = lane & 3;
    const int wm0 = (wid / WARPS_N) * 32, wn0 = (wid % WARPS_N) * WN;

    float acc[2][NT][4];
#pragma unroll
    for (int i = 0; i < 2; i++)
#pragma unroll
        for (int j = 0; j < NT; j++)
#pragma unroll
            for (int k = 0; k < 4; k++) acc[i][j][k] = 0.0f;

    auto issue = [&](int buf, int t) {
        int k0 = t * 32;
        uint32_t as = smem_u32(As + buf * BM * LDA);
        uint32_t bs = smem_u32(Bs + buf * 32 * LDB);
#pragma unroll
        for (int i = 0; i < AW; i++) {
            int q = tid + i * 256;
            int m = q >> 3, kq = q & 7;
            cpa16(as + (m * LDA + 4 * kq) * 4,
                  A + (long)(row0 + m) * lda + k0 + 4 * kq);
        }
#pragma unroll
        for (int i = 0; i < 2; i++) {
            int q = tid + i * 256;
            int kk = q >> 4, nq = q & 15;
            cpa16(bs + (kk * LDB + 4 * nq) * 4,
                  Bm + (long)(k0 + kk) * ldb + col0 + 4 * nq);
        }
        cp_commit();
    };
    auto compute = [&](int buf) {
        const uint32_t* ab = As + buf * BM * LDA;
        const uint32_t* bb = Bs + buf * 32 * LDB;
#pragma unroll
        for (int ks = 0; ks < 32; ks += 8) {
            uint32_t af[2][4], bf[NT][2];
#pragma unroll
            for (int mt = 0; mt < 2; mt++) {
                const uint32_t* p = ab + (wm0 + mt * 16 + gid) * LDA + ks + tg;
                af[mt][0] = tfb(p[0]);
                af[mt][1] = tfb(p[8 * LDA]);
                af[mt][2] = tfb(p[4]);
                af[mt][3] = tfb(p[8 * LDA + 4]);
            }
#pragma unroll
            for (int nt = 0; nt < NT; nt++) {
                const uint32_t* p = bb + (ks + tg) * LDB + wn0 + nt * 8 + gid;
                bf[nt][0] = tfb(p[0]);
                bf[nt][1] = tfb(p[4 * LDB]);
            }
#pragma unroll
            for (int mt = 0; mt < 2; mt++)
#pragma unroll
                for (int nt = 0; nt < NT; nt++)
                    mma_tf32(acc[mt][nt], af[mt], bf[nt]);
        }
    };

    const int TILES = K / 32;
    issue(0, 0);
    for (int t = 0; t < TILES; t++) {
        cp_wait<0>();
        __syncthreads();
        if (t + 1 < TILES) issue((t + 1) & 1, t + 1);
        compute(t & 1);
    }

#pragma unroll
    for (int mt = 0; mt < 2; mt++)
#pragma unroll
        for (int nt = 0; nt < NT; nt++)
#pragma unroll
            for (int half = 0; half < 2; half++) {
                int r = row0 + wm0 + mt * 16 + gid + half * 8;
                int c = col0 + wn0 + nt * 8 + 2 * tg;
                long off = (long)r * ldc + c;
                float v0 = acc[mt][nt][half * 2 + 0];
                float v1 = acc[mt][nt][half * 2 + 1];
                if (EPI == 2) {
                    float2 e = *(const float2*)(E + off);
                    v0 += e.x + bv[c];
                    v1 += e.y + bv[c + 1];
                } else if (EPI == 3) {
                    v0 += bv[c];
                    v1 += bv[c + 1];
                    v0 = 0.5f * v0 * (1.0f + erff(v0 * 0.70710678118654752f));
                    v1 = 0.5f * v1 * (1.0f + erff(v1 * 0.70710678118654752f));
                }
                float2 o; o.x = v0; o.y = v1;
                *(float2*)(C + off) = o;
            }
}

template <int EPI, int BM>
__global__ __launch_bounds__(256, 2)
void mma_gemm(const float* __restrict__ A, const float* __restrict__ Bm,
              float* __restrict__ C, const float* __restrict__ E,
              const float* __restrict__ bv,
              int K, int lda, int ldb, int ldc,
              long Ab, long Bb, long Cb) {
    extern __shared__ __align__(16) uint32_t smraw[];
    int z = blockIdx.z;
    A += (long)z * Ab;
    Bm += (long)z * Bb;
    long co = (long)z * Cb;
    gemm_core<EPI, BM>(A, Bm, C + co, (EPI == 2) ? E + co : E, bv,
                       K, lda, ldb, ldc, blockIdx.y * BM, blockIdx.x * 64, smraw);
}

// merged kv + q launch: blockIdx.x [0,8) -> kv (N=512), [8,12) -> q (N=256)
__global__ __launch_bounds__(256, 2)
void kvq_gemm(const float* __restrict__ xn, const float* __restrict__ Wkv,
              float* __restrict__ kv,
              const float* __restrict__ xma, const float* __restrict__ Wq,
              float* __restrict__ qo) {
    extern __shared__ __align__(16) uint32_t smraw[];
    int row0 = blockIdx.y * 128;
    if (blockIdx.x < 8)
        gemm_core<0, 128>(xn, Wkv, kv, nullptr, nullptr,
                          DIM, DIM, 2 * DIM, 2 * DIM, row0, blockIdx.x * 64, smraw);
    else
        gemm_core<0, 128>(xma, Wq, qo, nullptr, nullptr,
                          DIM, DIM, DIM, DIM, row0, (blockIdx.x - 8) * 64, smraw);
}

// ---------------- split-KV flash: each block does 512 keys, writes partials ----------------
__global__ __launch_bounds__(256)
void flash_kernel(const float* __restrict__ Qg, const float* __restrict__ KVg,
                  const __half* __restrict__ biasg) {
    extern __shared__ uint32_t sm[];
    uint32_t* Qs = sm;                    // [128][68] tf32
    uint32_t* Ks = Qs + 128 * 68;         // [2][128*68] raw fp32
    uint32_t* Vs = Ks + 2 * 128 * 68;     // [2][128*72] raw fp32

    const int qt = blockIdx.x & 7, split = blockIdx.x >> 3;
    const int i0 = qt * 128;
    const int h = blockIdx.y, b = blockIdx.z;
    const int bh = b * HEADS + h;
    const int P = bh * 2 + split;
    const float* Qp = Qg + (long)b * NN_ * DIM + h * DH;
    const float* Kp = KVg + (long)b * NN_ * 2 * DIM + h * DH;
    const float* Vp = Kp + DIM;
    const __half* Bp = biasg + (long)bh * NN_ * NN_ + (long)i0 * NN_;

    const int tid = threadIdx.x, wid = tid >> 5, lane = tid & 31;
    const int gid = lane >> 2, tg = lane & 3;
    const int wm0 = wid * 16;

    auto issue_kv = [&](int buf, int j0) {
        uint32_t ks = smem_u32(Ks + buf * 128 * 68);
        uint32_t vs = smem_u32(Vs + buf * 128 * 72);
#pragma unroll
        for (int t = 0; t < 8; t++) {
            int q = tid + t * 256;
            int n = q >> 4, c4 = (q & 15) << 2;
            cpa16(ks + (n * 68 + c4) * 4, Kp + (long)(j0 + n) * (2 * DIM) + c4);
            cpa16(vs + (n * 72 + c4) * 4, Vp + (long)(j0 + n) * (2 * DIM) + c4);
        }
        cp_commit();
    };

    const int jbase = split * 512;
    issue_kv(0, jbase);

#pragma unroll
    for (int t = 0; t < 8; t++) {
        int q = tid + t * 256;
        int m = q >> 4, c4 = (q & 15) << 2;
        float4 v = *(const float4*)(Qp + (long)(i0 + m) * DIM + c4);
        *(uint4*)(Qs + m * 68 + c4) = cvt4(v);
    }

    float oacc[8][4];
#pragma unroll
    for (int i = 0; i < 8; i++)
#pragma unroll
        for (int j = 0; j < 4; j++) oacc[i][j] = 0.0f;
    float mi0 = -1e30f, mi1 = -1e30f, li0 = 0.0f, li1 = 0.0f;

    for (int t = 0; t < 4; t++) {
        const int j0 = jbase + t * 128;
        const int buf = t & 1;
        cp_wait<0>();
        __syncthreads();
        if (t + 1 < 4) issue_kv(buf ^ 1, j0 + 128);

        const uint32_t* kb = Ks + buf * 128 * 68;
        const uint32_t* vb = Vs + buf * 128 * 72;

        float s[16][4];
#pragma unroll
        for (int i = 0; i < 16; i++)
#pragma unroll
            for (int j = 0; j < 4; j++) s[i][j] = 0.0f;
#pragma unroll
        for (int ks = 0; ks < 64; ks += 8) {
            uint32_t a[4];
            const uint32_t* pa = Qs + (wm0 + gid) * 68 + ks + tg;
            a[0] = pa[0];
            a[1] = pa[8 * 68];
            a[2] = pa[4];
            a[3] = pa[8 * 68 + 4];
#pragma unroll
            for (int nt = 0; nt < 16; nt++) {
                const uint32_t* pb = kb + (nt * 8 + gid) * 68 + ks + tg;
                uint32_t bf[2] = { tfb(pb[0]), tfb(pb[4]) };
                mma_tf32(s[nt], a, bf);
            }
        }

        float rmax0 = -1e30f, rmax1 = -1e30f;
#pragma unroll
        for (int nt = 0; nt < 16; nt++) {
            long o0 = (long)(wm0 + gid) * NN_ + j0 + nt * 8 + 2 * tg;
            float2 e0 = __half22float2(*(const __half2*)(Bp + o0));
            float2 e1 = __half22float2(*(const __half2*)(Bp + o0 + 8 * NN_));
            s[nt][0] = fmaf(s[nt][0], SCALE, e0.x);
            s[nt][1] = fmaf(s[nt][1], SCALE, e0.y);
            s[nt][2] = fmaf(s[nt][2], SCALE, e1.x);
            s[nt][3] = fmaf(s[nt][3], SCALE, e1.y);
            rmax0 = fmaxf(rmax0, fmaxf(s[nt][0], s[nt][1]));
            rmax1 = fmaxf(rmax1, fmaxf(s[nt][2], s[nt][3]));
        }
        rmax0 = fmaxf(rmax0, __shfl_xor_sync(0xffffffffu, rmax0, 1));
        rmax0 = fmaxf(rmax0, __shfl_xor_sync(0xffffffffu, rmax0, 2));
        rmax1 = fmaxf(rmax1, __shfl_xor_sync(0xffffffffu, rmax1, 1));
        rmax1 = fmaxf(rmax1, __shfl_xor_sync(0xffffffffu, rmax1, 2));
        float mn0 = fmaxf(mi0, rmax0), mn1 = fmaxf(mi1, rmax1);
        float al0 = __expf(mi0 - mn0), al1 = __expf(mi1 - mn1);
        float rs0 = 0.0f, rs1 = 0.0f;
#pragma unroll
        for (int nt = 0; nt < 16; nt++) {
            s[nt][0] = __expf(s[nt][0] - mn0); rs0 += s[nt][0];
            s[nt][1] = __expf(s[nt][1] - mn0); rs0 += s[nt][1];
            s[nt][2] = __expf(s[nt][2] - mn1); rs1 += s[nt][2];
            s[nt][3] = __expf(s[nt][3] - mn1); rs1 += s[nt][3];
        }
        rs0 += __shfl_xor_sync(0xffffffffu, rs0, 1);
        rs0 += __shfl_xor_sync(0xffffffffu, rs0, 2);
        rs1 += __shfl_xor_sync(0xffffffffu, rs1, 1);
        rs1 += __shfl_xor_sync(0xffffffffu, rs1, 2);
        li0 = li0 * al0 + rs0;
        li1 = li1 * al1 + rs1;
        mi0 = mn0; mi1 = mn1;
#pragma unroll
        for (int nt = 0; nt < 8; nt++) {
            oacc[nt][0] *= al0; oacc[nt][1] *= al0;
            oacc[nt][2] *= al1; oacc[nt][3] *= al1;
        }

        const int src = (lane & ~3) | (tg >> 1);
        const bool odd = (tg & 1);
#pragma unroll
        for (int g = 0; g < 16; g++) {
            float f0 = __shfl_sync(0xffffffffu, s[g][0], src);
            float f1 = __shfl_sync(0xffffffffu, s[g][1], src);
            float f2 = __shfl_sync(0xffffffffu, s[g][0], src + 2);
            float f3 = __shfl_sync(0xffffffffu, s[g][1], src + 2);
            float h0 = __shfl_sync(0xffffffffu, s[g][2], src);
            float h1 = __shfl_sync(0xffffffffu, s[g][3], src);
            float h2 = __shfl_sync(0xffffffffu, s[g][2], src + 2);
            float h3 = __shfl_sync(0xffffffffu, s[g][3], src + 2);
            uint32_t pa4[4];
            pa4[0] = f2tf(odd ? f1 : f0);
            pa4[1] = f2tf(odd ? h1 : h0);
            pa4[2] = f2tf(odd ? f3 : f2);
            pa4[3] = f2tf(odd ? h3 : h2);
#pragma unroll
            for (int nt = 0; nt < 8; nt++) {
                const uint32_t* pb = vb + (g * 8 + tg) * 72 + nt * 8 + gid;
                uint32_t bf[2] = { tfb(pb[0]), tfb(pb[4 * 72]) };
                mma_tf32(oacc[nt], pa4, bf);
            }
        }
    }

    // write unnormalized partials + (m, l)
    const int r0 = i0 + wm0 + gid;
#pragma unroll
    for (int nt = 0; nt < 8; nt++) {
        long off = ((long)P * NN_ + r0) * DH + nt * 8 + 2 * tg;
        float2 o0; o0.x = oacc[nt][0]; o0.y = oacc[nt][1];
        float2 o1; o1.x = oacc[nt][2]; o1.y = oacc[nt][3];
        *(float2*)(g_opart + off) = o0;
        *(float2*)(g_opart + off + 8 * DH) = o1;
    }
    if (tg == 0) {
        g_mlp[(long)P * NN_ + r0] = make_float2(mi0, li0);
        g_mlp[(long)P * NN_ + r0 + 8] = make_float2(mi1, li1);
    }
}

// combine the 2 KV-splits -> g_ao (heads concatenated)
__global__ __launch_bounds__(256)
void combine_kernel(float* __restrict__ Og) {
    int idx = blockIdx.x * 256 + threadIdx.x;   // total B*H*N*DH/4 = 262144
    int d4 = (idx & 15) * 4;
    int row = idx >> 4;            // (b*H + h)*N + i
    int bh = row >> 10;
    int i = row & 1023;
    long o0 = ((long)(bh * 2 + 0) * NN_ + i) * DH + d4;
    long o1 = ((long)(bh * 2 + 1) * NN_ + i) * DH + d4;
    float2 ml0 = g_mlp[(long)(bh * 2 + 0) * NN_ + i];
    float2 ml1 = g_mlp[(long)(bh * 2 + 1) * NN_ + i];
    float m = fmaxf(ml0.x, ml1.x);
    float w0 = __expf(ml0.x - m), w1 = __expf(ml1.x - m);
    float inv = 1.0f / (w0 * ml0.y + w1 * ml1.y);
    float4 a = *(const float4*)(g_opart + o0);
    float4 c = *(const float4*)(g_opart + o1);
    float4 o;
    o.x = (w0 * a.x + w1 * c.x) * inv;
    o.y = (w0 * a.y + w1 * c.y) * inv;
    o.z = (w0 * a.z + w1 * c.z) * inv;
    o.w = (w0 * a.w + w1 * c.w) * inv;
    int b = bh >> 2, h = bh & 3;
    *(float4*)(Og + ((long)b * NN_ + i) * DIM + h * DH + d4) = o;
}

// ---------------- prep: add_attn(fp16) ; G = softmax(mean(b0)*mean(b1)) ----------
__global__ __launch_bounds__(256)
void prep_kernel(const float* __restrict__ ab) {
    __shared__ float sh[32];
    int b = blockIdx.x >> 10;
    int i = blockIdx.x & 1023;
    const long BHNN = (long)BB * HEADS * NN_ * NN_;
    int tid = threadIdx.x;
    int j4 = tid * 4;
    float4 sa = make_float4(0, 0, 0, 0), sb = make_float4(0, 0, 0, 0);
#pragma unroll
    for (int h = 0; h < HEADS; h++) {
        long o = (((long)(b * HEADS + h) * NN_) + i) * NN_ + j4;
        float4 a0 = *(const float4*)(ab + o);
        float4 a1 = *(const float4*)(ab + BHNN + o);
        sa.x += a0.x; sa.y += a0.y; sa.z += a0.z; sa.w += a0.w;
        sb.x += a1.x; sb.y += a1.y; sb.z += a1.z; sb.w += a1.w;
        union { __half2 h2[2]; uint2 u; } pk;
        pk.h2[0] = __floats2half2_rn(a0.x + a1.x, a0.y + a1.y);
        pk.h2[1] = __floats2half2_rn(a0.z + a1.z, a0.w + a1.w);
        *(uint2*)(&g_bias[o]) = pk.u;
    }
    float val[4];
    val[0] = (sa.x * 0.25f) * (sb.x * 0.25f);
    val[1] = (sa.y * 0.25f) * (sb.y * 0.25f);
    val[2] = (sa.z * 0.25f) * (sb.z * 0.25f);
    val[3] = (sa.w * 0.25f) * (sb.w * 0.25f);
    float m = fmaxf(fmaxf(val[0], val[1]), fmaxf(val[2], val[3]));
    m = block_max(m, sh);
    float s = 0.0f;
#pragma unroll
    for (int t = 0; t < 4; t++) { val[t] = __expf(val[t] - m); s += val[t]; }
    s = block_sum(s, sh);
    float inv = 1.0f / s;
    long rowo = ((long)(b * NN_ + i)) * NN_ + j4;
    float4 g4; g4.x = val[0] * inv; g4.y = val[1] * inv; g4.z = val[2] * inv; g4.w = val[3] * inv;
    *(float4*)(g_G + rowo) = g4;
}

// ---------------- LayerNorm: one warp/row, one-pass ----------------
__device__ __forceinline__ void ln_row(const float* __restrict__ in, float* __restrict__ out,
                                       const float* __restrict__ g, const float* __restrict__ bt,
                                       long row, int lane, int relu) {
    const float* p = in + row * DIM + lane * 8;
    float4 v0 = *(const float4*)p;
    float4 v1 = *(const float4*)(p + 4);
    float s = v0.x + v0.y + v0.z + v0.w + v1.x + v1.y + v1.z + v1.w;
    float q = v0.x * v0.x + v0.y * v0.y + v0.z * v0.z + v0.w * v0.w
            + v1.x * v1.x + v1.y * v1.y + v1.z * v1.z + v1.w * v1.w;
#pragma unroll
    for (int o = 16; o; o >>= 1) {
        s += __shfl_xor_sync(0xffffffffu, s, o);
        q += __shfl_xor_sync(0xffffffffu, q, o);
    }
    float mean = s * (1.0f / DIM);
    float var = q * (1.0f / DIM) - mean * mean;
    float rstd = rsqrtf(var + EPS);
    const float* gp = g + lane * 8;
    const float* bp = bt + lane * 8;
    float4 g0 = *(const float4*)gp, g1 = *(const float4*)(gp + 4);
    float4 b0 = *(const float4*)bp, b1 = *(const float4*)(bp + 4);
    float o8[8];
    o8[0] = (v0.x - mean) * rstd * g0.x + b0.x; o8[1] = (v0.y - mean) * rstd * g0.y + b0.y;
    o8[2] = (v0.z - mean) * rstd * g0.z + b0.z; o8[3] = (v0.w - mean) * rstd * g0.w + b0.w;
    o8[4] = (v1.x - mean) * rstd * g1.x + b1.x; o8[5] = (v1.y - mean) * rstd * g1.y + b1.y;
    o8[6] = (v1.z - mean) * rstd * g1.z + b1.z; o8[7] = (v1.w - mean) * rstd * g1.w + b1.w;
    if (relu) {
#pragma unroll
        for (int t = 0; t < 8; t++) o8[t] = fmaxf(o8[t], 0.0f);
    }
    float* po = out + row * DIM + lane * 8;
    float4 r0; r0.x = o8[0]; r0.y = o8[1]; r0.z = o8[2]; r0.w = o8[3];
    float4 r1; r1.x = o8[4]; r1.y = o8[5]; r1.z = o8[6]; r1.w = o8[7];
    *(float4*)po = r0;
    *(float4*)(po + 4) = r1;
}

__global__ __launch_bounds__(256)
void ln_one(const float* __restrict__ in, float* __restrict__ out,
            const float* __restrict__ g, const float* __restrict__ bt) {
    int w = threadIdx.x >> 5, lane = threadIdx.x & 31;
    ln_row(in, out, g, bt, (long)blockIdx.x * 8 + w, lane, 0);
}

__global__ __launch_bounds__(256)
void ln_fused(const float* __restrict__ inA, float* __restrict__ outA,
              const float* __restrict__ gA, const float* __restrict__ bA,
              const float* __restrict__ inB, float* __restrict__ outB,
              const float* __restrict__ gB, const float* __restrict__ bB, int nA) {
    int w = threadIdx.x >> 5, lane = threadIdx.x & 31;
    int bid = blockIdx.x;
    if (bid < nA)
        ln_row(inA, outA, gA, bA, (long)bid * 8 + w, lane, 1);
    else
        ln_row(inB, outB, gB, bB, (long)(bid - nA) * 8 + w, lane, 0);
}

// ---------------- host ----------------
extern "C" void kernel_launch(void* const* d_in, const int* in_sizes, int n_in,
                              void* d_out, int out_size) {
    const float* x_in   = (const float*)d_in[0];
    const float* abias  = (const float*)d_in[1];
    const float* ln1_g  = (const float*)d_in[2];
    const float* ln1_b  = (const float*)d_in[3];
    const float* Wkv    = (const float*)d_in[4];
    const float* Wq     = (const float*)d_in[5];
    const float* Wo     = (const float*)d_in[6];
    const float* bo     = (const float*)d_in[7];
    const float* ln2_g  = (const float*)d_in[8];
    const float* ln2_b  = (const float*)d_in[9];
    const float* W1     = (const float*)d_in[10];
    const float* b1     = (const float*)d_in[11];
    const float* W2     = (const float*)d_in[12];
    const float* b2     = (const float*)d_in[13];
    const float* Wg     = (const float*)d_in[14];
    const float* lng_g  = (const float*)d_in[15];
    const float* lng_b  = (const float*)d_in[16];
    float* out = (float*)d_out;

    float *px, *pxn, *pxma, *pq, *pkv, *pao, *pG, *pff;
    __half* pbias;
    cudaGetSymbolAddress((void**)&px, g_x);
    cudaGetSymbolAddress((void**)&pxn, g_xn);
    cudaGetSymbolAddress((void**)&pxma, g_xma);
    cudaGetSymbolAddress((void**)&pq, g_q);
    cudaGetSymbolAddress((void**)&pkv, g_kv);
    cudaGetSymbolAddress((void**)&pao, g_ao);
    cudaGetSymbolAddress((void**)&pG, g_G);
    cudaGetSymbolAddress((void**)&pbias, g_bias);
    cudaGetSymbolAddress((void**)&pff, g_ff);

    const int ROWS = BB * NN_;           // 4096
    const long ND = (long)NN_ * DIM;
    dim3 blk(256);

    const int SM_G128 = (2 * 128 * LDA + 2 * 32 * LDB) * 4;   // 55296
    const int SM_G64  = (2 * 64 * LDA + 2 * 32 * LDB) * 4;    // 36864
    const int SM_FL = (128 * 68 + 2 * 128 * 68 + 2 * 128 * 72) * 4;  // 178176
    cudaFuncSetAttribute(mma_gemm<0, 128>, cudaFuncAttributeMaxDynamicSharedMemorySize, SM_G128);
    cudaFuncSetAttribute(mma_gemm<3, 128>, cudaFuncAttributeMaxDynamicSharedMemorySize, SM_G128);
    cudaFuncSetAttribute(mma_gemm<0, 64>, cudaFuncAttributeMaxDynamicSharedMemorySize, SM_G64);
    cudaFuncSetAttribute(mma_gemm<2, 64>, cudaFuncAttributeMaxDynamicSharedMemorySize, SM_G64);
    cudaFuncSetAttribute(kvq_gemm, cudaFuncAttributeMaxDynamicSharedMemorySize, SM_G128);
    cudaFuncSetAttribute(flash_kernel, cudaFuncAttributeMaxDynamicSharedMemorySize, SM_FL);

    prep_kernel<<<BB * NN_, blk>>>(abias);

    for (int l = 0; l < DEPTH; l++) {
        const float* xcur = (l == 0) ? x_in : px;
        // GX = G @ x -> g_xn   [per b: 1024x256, K=1024] (256 blocks)
        mma_gemm<0, 128><<<dim3(DIM / 64, NN_ / 128, BB), blk, SM_G128>>>(
            pG, xcur, pxn, nullptr, nullptr,
            NN_, NN_, DIM, DIM, (long)NN_ * NN_, ND, ND);
        // x_ma_pre = GX @ Wg -> g_xma  (256 blocks, BM=64)
        mma_gemm<0, 64><<<dim3(DIM / 64, ROWS / 64, 1), blk, SM_G64>>>(
            pxn, Wg, pxma, nullptr, nullptr,
            DIM, DIM, DIM, DIM, 0, 0, 0);
        // merged: x_ma = relu(LN(x_ma)) ; xn = LN(x)
        ln_fused<<<ROWS / 4, blk>>>(pxma, pxma, lng_g, lng_b,
                                    xcur, pxn, ln1_g + l * DIM, ln1_b + l * DIM, ROWS / 8);
        // merged kv + q (384 blocks)
        kvq_gemm<<<dim3(12, ROWS / 128, 1), blk, SM_G128>>>(
            pxn, Wkv + (long)l * DIM * 2 * DIM, pkv,
            pxma, Wq + (long)l * DIM * DIM, pq);
        // split-KV flash (256 blocks) + combine
        flash_kernel<<<dim3(16, HEADS, BB), blk, SM_FL>>>(pq, pkv, pbias);
        combine_kernel<<<1024, blk>>>(pao);
        // x = x + out @ Wo[l] + bo[l]  (256 blocks, BM=64)
        mma_gemm<2, 64><<<dim3(DIM / 64, ROWS / 64, 1), blk, SM_G64>>>(
            pao, Wo + (long)l * DIM * DIM, px, xcur, bo + l * DIM,
            DIM, DIM, DIM, DIM, 0, 0, 0);
        // xn2 = LN(x)
        ln_one<<<ROWS / 8, blk>>>(px, pxn, ln2_g + l * DIM, ln2_b + l * DIM);
        // ff = gelu(xn2 @ W1[l] + b1[l])  (512 blocks)
        mma_gemm<3, 128><<<dim3(MLP / 64, ROWS / 128, 1), blk, SM_G128>>>(
            pxn, W1 + (long)l * DIM * MLP, pff, nullptr, b1 + l * MLP,
            DIM, DIM, MLP, MLP, 0, 0, 0);
        // x = x + ff @ W2[l] + b2[l]  (256 blocks, BM=64; last layer -> d_out)
        float* cdst = (l == DEPTH - 1) ? out : px;
        mma_gemm<2, 64><<<dim3(DIM / 64, ROWS / 64, 1), blk, SM_G64>>>(
            pff, W2 + (long)l * MLP * DIM, cdst, px, b2 + l * DIM,
            MLP, MLP, DIM, DIM, 0, 0, 0);
    }
}

// round 7
// speedup vs baseline: 1.5823x; 1.5823x over previous
#include <cuda_runtime.h>
#include <cuda_fp16.h>
#include <math.h>
#include <stdint.h>

#define BB 4
#define NN_ 1024
#define DIM 256
#define HEADS 4
#define DH 64
#define DEPTH 4
#define MLP 1024
#define EPS 1e-5f
#define SCALE 0.0625f   // DIM^-0.5

// ---------------- scratch ----------------
__device__ float g_x  [BB*NN_*DIM];
__device__ float g_xn [BB*NN_*DIM];
__device__ float g_xma[BB*NN_*DIM];
__device__ float g_q  [BB*NN_*DIM];
__device__ float g_kv [BB*NN_*2*DIM];
__device__ float g_ao [BB*NN_*DIM];
__device__ float g_G  [(long)BB*NN_*NN_];
__device__ __half g_bias[(long)BB*HEADS*NN_*NN_];
__device__ float g_ff [BB*NN_*MLP];

// ---------------- helpers ----------------
__device__ __forceinline__ float warp_sum(float v) {
#pragma unroll
    for (int o = 16; o; o >>= 1) v += __shfl_xor_sync(0xffffffffu, v, o);
    return v;
}
__device__ __forceinline__ float warp_max(float v) {
#pragma unroll
    for (int o = 16; o; o >>= 1) v = fmaxf(v, __shfl_xor_sync(0xffffffffu, v, o));
    return v;
}
__device__ __forceinline__ float block_sum(float v, float* sh) {
    int lane = threadIdx.x & 31, w = threadIdx.x >> 5;
    v = warp_sum(v);
    if (lane == 0) sh[w] = v;
    __syncthreads();
    v = (lane < 8) ? sh[lane] : 0.0f;
    v = warp_sum(v);
    __syncthreads();
    return v;
}
__device__ __forceinline__ float block_max(float v, float* sh) {
    int lane = threadIdx.x & 31, w = threadIdx.x >> 5;
    v = warp_max(v);
    if (lane == 0) sh[w] = v;
    __syncthreads();
    v = (lane < 8) ? sh[lane] : -INFINITY;
    v = warp_max(v);
    __syncthreads();
    return v;
}

__device__ __forceinline__ uint32_t f2tf(float f) {
    uint32_t u;
    asm("cvt.rna.tf32.f32 %0, %1;" : "=r"(u) : "f"(f));
    return u;
}
__device__ __forceinline__ uint32_t tfb(uint32_t bits) {
    return f2tf(__uint_as_float(bits));
}
__device__ __forceinline__ void mma_tf32(float c[4], const uint32_t a[4], const uint32_t b[2]) {
    asm volatile(
        "mma.sync.aligned.m16n8k8.row.col.f32.tf32.tf32.f32 "
        "{%0,%1,%2,%3}, {%4,%5,%6,%7}, {%8,%9}, {%0,%1,%2,%3};"
        : "+f"(c[0]), "+f"(c[1]), "+f"(c[2]), "+f"(c[3])
        : "r"(a[0]), "r"(a[1]), "r"(a[2]), "r"(a[3]), "r"(b[0]), "r"(b[1]));
}
__device__ __forceinline__ uint4 cvt4(float4 v) {
    return make_uint4(f2tf(v.x), f2tf(v.y), f2tf(v.z), f2tf(v.w));
}
__device__ __forceinline__ uint32_t smem_u32(const void* p) {
    return (uint32_t)__cvta_generic_to_shared(p);
}
__device__ __forceinline__ void cpa16(uint32_t dst, const void* src) {
    asm volatile("cp.async.cg.shared.global [%0], [%1], 16;" :: "r"(dst), "l"(src));
}
__device__ __forceinline__ void cp_commit() { asm volatile("cp.async.commit_group;"); }
template <int N> __device__ __forceinline__ void cp_wait() {
    asm volatile("cp.async.wait_group %0;" :: "n"(N));
}

// ---------------- dense GEMM core: BM=128 BN=64 WM=32 WN=32 BK=32, 3-stage, 2 CTA/SM ------
// smem: 3*(128*36 + 32*72)*4 = 82944 B; x2 CTAs = 165888 <= 228KB
#define LDA 36
#define LDB 72
#define STG 3
#define STAGE_WORDS (128 * LDA + 32 * LDB)
#define SM_G (STG * STAGE_WORDS * 4)

template <int EPI>
__device__ __forceinline__ void gemm_core(
    const float* __restrict__ A, const float* __restrict__ Bm,
    float* __restrict__ C, const float* __restrict__ E, const float* __restrict__ bv,
    int K, int lda, int ldb, int ldc, int row0, int col0, uint32_t* smraw) {

    const int tid = threadIdx.x, wid = tid >> 5, lane = tid & 31;
    const int gid = lane >> 2, tg = lane & 3;
    const int wm0 = (wid >> 1) * 32, wn0 = (wid & 1) * 32;

    float acc[2][4][4];
#pragma unroll
    for (int i = 0; i < 2; i++)
#pragma unroll
        for (int j = 0; j < 4; j++)
#pragma unroll
            for (int k = 0; k < 4; k++) acc[i][j][k] = 0.0f;

    auto issue = [&](int buf, int t) {
        int k0 = t * 32;
        uint32_t as = smem_u32(smraw + buf * STAGE_WORDS);
        uint32_t bs = as + 128 * LDA * 4;
#pragma unroll
        for (int i = 0; i < 4; i++) {
            int q = tid + i * 256;
            int m = q >> 3, kq = q & 7;
            cpa16(as + (m * LDA + 4 * kq) * 4,
                  A + (long)(row0 + m) * lda + k0 + 4 * kq);
        }
#pragma unroll
        for (int i = 0; i < 2; i++) {
            int q = tid + i * 256;
            int kk = q >> 4, nq = q & 15;
            cpa16(bs + (kk * LDB + 4 * nq) * 4,
                  Bm + (long)(k0 + kk) * ldb + col0 + 4 * nq);
        }
        cp_commit();
    };
    auto compute = [&](int buf) {
        const uint32_t* ab = smraw + buf * STAGE_WORDS;
        const uint32_t* bb = ab + 128 * LDA;
#pragma unroll
        for (int ks = 0; ks < 32; ks += 8) {
            uint32_t af[2][4], bf[4][2];
#pragma unroll
            for (int mt = 0; mt < 2; mt++) {
                const uint32_t* p = ab + (wm0 + mt * 16 + gid) * LDA + ks + tg;
                af[mt][0] = tfb(p[0]);
                af[mt][1] = tfb(p[8 * LDA]);
                af[mt][2] = tfb(p[4]);
                af[mt][3] = tfb(p[8 * LDA + 4]);
            }
#pragma unroll
            for (int nt = 0; nt < 4; nt++) {
                const uint32_t* p = bb + (ks + tg) * LDB + wn0 + nt * 8 + gid;
                bf[nt][0] = tfb(p[0]);
                bf[nt][1] = tfb(p[4 * LDB]);
            }
#pragma unroll
            for (int mt = 0; mt < 2; mt++)
#pragma unroll
                for (int nt = 0; nt < 4; nt++)
                    mma_tf32(acc[mt][nt], af[mt], bf[nt]);
        }
    };

    const int TILES = K / 32;
    issue(0, 0);
    if (TILES > 1) issue(1, 1);
    else cp_commit();
    int buf = 0, nxt = 2;
    for (int t = 0; t < TILES; t++) {
        cp_wait<STG - 2>();
        __syncthreads();
        if (t + 2 < TILES) issue(nxt, t + 2);
        else cp_commit();
        compute(buf);
        buf = (buf + 1 == STG) ? 0 : buf + 1;
        nxt = (nxt + 1 == STG) ? 0 : nxt + 1;
        __syncthreads();
    }

#pragma unroll
    for (int mt = 0; mt < 2; mt++)
#pragma unroll
        for (int nt = 0; nt < 4; nt++)
#pragma unroll
            for (int half = 0; half < 2; half++) {
                int r = row0 + wm0 + mt * 16 + gid + half * 8;
                int c = col0 + wn0 + nt * 8 + 2 * tg;
                long off = (long)r * ldc + c;
                float v0 = acc[mt][nt][half * 2 + 0];
                float v1 = acc[mt][nt][half * 2 + 1];
                if (EPI == 2) {
                    float2 e = *(const float2*)(E + off);
                    v0 += e.x + bv[c];
                    v1 += e.y + bv[c + 1];
                } else if (EPI == 3) {
                    v0 += bv[c];
                    v1 += bv[c + 1];
                    v0 = 0.5f * v0 * (1.0f + erff(v0 * 0.70710678118654752f));
                    v1 = 0.5f * v1 * (1.0f + erff(v1 * 0.70710678118654752f));
                }
                float2 o; o.x = v0; o.y = v1;
                *(float2*)(C + off) = o;
            }
}

template <int EPI>
__global__ __launch_bounds__(256, 2)
void mma_gemm(const float* __restrict__ A, const float* __restrict__ Bm,
              float* __restrict__ C, const float* __restrict__ E,
              const float* __restrict__ bv,
              int K, int lda, int ldb, int ldc,
              long Ab, long Bb, long Cb) {
    extern __shared__ __align__(16) uint32_t smraw[];
    int z = blockIdx.z;
    A += (long)z * Ab;
    Bm += (long)z * Bb;
    long co = (long)z * Cb;
    gemm_core<EPI>(A, Bm, C + co, (EPI == 2) ? E + co : E, bv,
                   K, lda, ldb, ldc, blockIdx.y * 128, blockIdx.x * 64, smraw);
}

// merged kv + q launch: blockIdx.x [0,8) -> kv (N=512), [8,12) -> q (N=256)
__global__ __launch_bounds__(256, 2)
void kvq_gemm(const float* __restrict__ xn, const float* __restrict__ Wkv,
              float* __restrict__ kv,
              const float* __restrict__ xma, const float* __restrict__ Wq,
              float* __restrict__ qo) {
    extern __shared__ __align__(16) uint32_t smraw[];
    int row0 = blockIdx.y * 128;
    if (blockIdx.x < 8)
        gemm_core<0>(xn, Wkv, kv, nullptr, nullptr,
                     DIM, DIM, 2 * DIM, 2 * DIM, row0, blockIdx.x * 64, smraw);
    else
        gemm_core<0>(xma, Wq, qo, nullptr, nullptr,
                     DIM, DIM, DIM, DIM, row0, (blockIdx.x - 8) * 64, smraw);
}

// ---------------- fused flash attention (R5 structure: 128 q-rows, full KV sweep) ---------
__global__ __launch_bounds__(256)
void flash_kernel(const float* __restrict__ Qg, const float* __restrict__ KVg,
                  const __half* __restrict__ biasg, float* __restrict__ Og) {
    extern __shared__ uint32_t sm[];
    uint32_t* Qs = sm;                    // [128][68] tf32
    uint32_t* Ks = Qs + 128 * 68;         // [2][128*68] raw fp32
    uint32_t* Vs = Ks + 2 * 128 * 68;     // [2][128*72] raw fp32

    const int i0 = blockIdx.x * 128;
    const int h = blockIdx.y, b = blockIdx.z;
    const float* Qp = Qg + (long)b * NN_ * DIM + h * DH;
    const float* Kp = KVg + (long)b * NN_ * 2 * DIM + h * DH;
    const float* Vp = Kp + DIM;
    const __half* Bp = biasg + ((long)(b * HEADS + h)) * NN_ * NN_ + (long)i0 * NN_;

    const int tid = threadIdx.x, wid = tid >> 5, lane = tid & 31;
    const int gid = lane >> 2, tg = lane & 3;
    const int wm0 = wid * 16;

    auto issue_kv = [&](int buf, int j0) {
        uint32_t ks = smem_u32(Ks + buf * 128 * 68);
        uint32_t vs = smem_u32(Vs + buf * 128 * 72);
#pragma unroll
        for (int t = 0; t < 8; t++) {
            int q = tid + t * 256;
            int n = q >> 4, c4 = (q & 15) << 2;
            cpa16(ks + (n * 68 + c4) * 4, Kp + (long)(j0 + n) * (2 * DIM) + c4);
            cpa16(vs + (n * 72 + c4) * 4, Vp + (long)(j0 + n) * (2 * DIM) + c4);
        }
        cp_commit();
    };

    issue_kv(0, 0);

#pragma unroll
    for (int t = 0; t < 8; t++) {
        int q = tid + t * 256;
        int m = q >> 4, c4 = (q & 15) << 2;
        float4 v = *(const float4*)(Qp + (long)(i0 + m) * DIM + c4);
        *(uint4*)(Qs + m * 68 + c4) = cvt4(v);
    }

    float oacc[8][4];
#pragma unroll
    for (int i = 0; i < 8; i++)
#pragma unroll
        for (int j = 0; j < 4; j++) oacc[i][j] = 0.0f;
    float mi0 = -1e30f, mi1 = -1e30f, li0 = 0.0f, li1 = 0.0f;

    for (int t = 0; t < NN_ / 128; t++) {
        const int j0 = t * 128;
        const int buf = t & 1;
        cp_wait<0>();
        __syncthreads();
        if (t + 1 < NN_ / 128) issue_kv(buf ^ 1, j0 + 128);

        const uint32_t* kb = Ks + buf * 128 * 68;
        const uint32_t* vb = Vs + buf * 128 * 72;

        float s[16][4];
#pragma unroll
        for (int i = 0; i < 16; i++)
#pragma unroll
            for (int j = 0; j < 4; j++) s[i][j] = 0.0f;
#pragma unroll
        for (int ks = 0; ks < 64; ks += 8) {
            uint32_t a[4];
            const uint32_t* pa = Qs + (wm0 + gid) * 68 + ks + tg;
            a[0] = pa[0];
            a[1] = pa[8 * 68];
            a[2] = pa[4];
            a[3] = pa[8 * 68 + 4];
#pragma unroll
            for (int nt = 0; nt < 16; nt++) {
                const uint32_t* pb = kb + (nt * 8 + gid) * 68 + ks + tg;
                uint32_t bf[2] = { tfb(pb[0]), tfb(pb[4]) };
                mma_tf32(s[nt], a, bf);
            }
        }

        float rmax0 = -1e30f, rmax1 = -1e30f;
#pragma unroll
        for (int nt = 0; nt < 16; nt++) {
            long o0 = (long)(wm0 + gid) * NN_ + j0 + nt * 8 + 2 * tg;
            float2 e0 = __half22float2(*(const __half2*)(Bp + o0));
            float2 e1 = __half22float2(*(const __half2*)(Bp + o0 + 8 * NN_));
            s[nt][0] = fmaf(s[nt][0], SCALE, e0.x);
            s[nt][1] = fmaf(s[nt][1], SCALE, e0.y);
            s[nt][2] = fmaf(s[nt][2], SCALE, e1.x);
            s[nt][3] = fmaf(s[nt][3], SCALE, e1.y);
            rmax0 = fmaxf(rmax0, fmaxf(s[nt][0], s[nt][1]));
            rmax1 = fmaxf(rmax1, fmaxf(s[nt][2], s[nt][3]));
        }
        rmax0 = fmaxf(rmax0, __shfl_xor_sync(0xffffffffu, rmax0, 1));
        rmax0 = fmaxf(rmax0, __shfl_xor_sync(0xffffffffu, rmax0, 2));
        rmax1 = fmaxf(rmax1, __shfl_xor_sync(0xffffffffu, rmax1, 1));
        rmax1 = fmaxf(rmax1, __shfl_xor_sync(0xffffffffu, rmax1, 2));
        float mn0 = fmaxf(mi0, rmax0), mn1 = fmaxf(mi1, rmax1);
        float al0 = __expf(mi0 - mn0), al1 = __expf(mi1 - mn1);
        float rs0 = 0.0f, rs1 = 0.0f;
#pragma unroll
        for (int nt = 0; nt < 16; nt++) {
            s[nt][0] = __expf(s[nt][0] - mn0); rs0 += s[nt][0];
            s[nt][1] = __expf(s[nt][1] - mn0); rs0 += s[nt][1];
            s[nt][2] = __expf(s[nt][2] - mn1); rs1 += s[nt][2];
            s[nt][3] = __expf(s[nt][3] - mn1); rs1 += s[nt][3];
        }
        rs0 += __shfl_xor_sync(0xffffffffu, rs0, 1);
        rs0 += __shfl_xor_sync(0xffffffffu, rs0, 2);
        rs1 += __shfl_xor_sync(0xffffffffu, rs1, 1);
        rs1 += __shfl_xor_sync(0xffffffffu, rs1, 2);
        li0 = li0 * al0 + rs0;
        li1 = li1 * al1 + rs1;
        mi0 = mn0; mi1 = mn1;
#pragma unroll
        for (int nt = 0; nt < 8; nt++) {
            oacc[nt][0] *= al0; oacc[nt][1] *= al0;
            oacc[nt][2] *= al1; oacc[nt][3] *= al1;
        }

        const int src = (lane & ~3) | (tg >> 1);
        const bool odd = (tg & 1);
#pragma unroll
        for (int g = 0; g < 16; g++) {
            float f0 = __shfl_sync(0xffffffffu, s[g][0], src);
            float f1 = __shfl_sync(0xffffffffu, s[g][1], src);
            float f2 = __shfl_sync(0xffffffffu, s[g][0], src + 2);
            float f3 = __shfl_sync(0xffffffffu, s[g][1], src + 2);
            float h0 = __shfl_sync(0xffffffffu, s[g][2], src);
            float h1 = __shfl_sync(0xffffffffu, s[g][3], src);
            float h2 = __shfl_sync(0xffffffffu, s[g][2], src + 2);
            float h3 = __shfl_sync(0xffffffffu, s[g][3], src + 2);
            uint32_t pa4[4];
            pa4[0] = f2tf(odd ? f1 : f0);
            pa4[1] = f2tf(odd ? h1 : h0);
            pa4[2] = f2tf(odd ? f3 : f2);
            pa4[3] = f2tf(odd ? h3 : h2);
#pragma unroll
            for (int nt = 0; nt < 8; nt++) {
                const uint32_t* pb = vb + (g * 8 + tg) * 72 + nt * 8 + gid;
                uint32_t bf[2] = { tfb(pb[0]), tfb(pb[4 * 72]) };
                mma_tf32(oacc[nt], pa4, bf);
            }
        }
    }

    float iv0 = 1.0f / li0, iv1 = 1.0f / li1;
#pragma unroll
    for (int nt = 0; nt < 8; nt++) {
        long off = ((long)b * NN_ + i0 + wm0 + gid) * DIM + h * DH + nt * 8 + 2 * tg;
        float2 o0; o0.x = oacc[nt][0] * iv0; o0.y = oacc[nt][1] * iv0;
        float2 o1; o1.x = oacc[nt][2] * iv1; o1.y = oacc[nt][3] * iv1;
        *(float2*)(Og + off) = o0;
        *(float2*)(Og + off + 8 * DIM) = o1;
    }
}

// ---------------- prep: add_attn(fp16) ; G = softmax(mean(b0)*mean(b1)) ----------
__global__ __launch_bounds__(256)
void prep_kernel(const float* __restrict__ ab) {
    __shared__ float sh[32];
    int b = blockIdx.x >> 10;
    int i = blockIdx.x & 1023;
    const long BHNN = (long)BB * HEADS * NN_ * NN_;
    int tid = threadIdx.x;
    int j4 = tid * 4;
    float4 sa = make_float4(0, 0, 0, 0), sb = make_float4(0, 0, 0, 0);
#pragma unroll
    for (int h = 0; h < HEADS; h++) {
        long o = (((long)(b * HEADS + h) * NN_) + i) * NN_ + j4;
        float4 a0 = *(const float4*)(ab + o);
        float4 a1 = *(const float4*)(ab + BHNN + o);
        sa.x += a0.x; sa.y += a0.y; sa.z += a0.z; sa.w += a0.w;
        sb.x += a1.x; sb.y += a1.y; sb.z += a1.z; sb.w += a1.w;
        union { __half2 h2[2]; uint2 u; } pk;
        pk.h2[0] = __floats2half2_rn(a0.x + a1.x, a0.y + a1.y);
        pk.h2[1] = __floats2half2_rn(a0.z + a1.z, a0.w + a1.w);
        *(uint2*)(&g_bias[o]) = pk.u;
    }
    float val[4];
    val[0] = (sa.x * 0.25f) * (sb.x * 0.25f);
    val[1] = (sa.y * 0.25f) * (sb.y * 0.25f);
    val[2] = (sa.z * 0.25f) * (sb.z * 0.25f);
    val[3] = (sa.w * 0.25f) * (sb.w * 0.25f);
    float m = fmaxf(fmaxf(val[0], val[1]), fmaxf(val[2], val[3]));
    m = block_max(m, sh);
    float s = 0.0f;
#pragma unroll
    for (int t = 0; t < 4; t++) { val[t] = __expf(val[t] - m); s += val[t]; }
    s = block_sum(s, sh);
    float inv = 1.0f / s;
    long rowo = ((long)(b * NN_ + i)) * NN_ + j4;
    float4 g4; g4.x = val[0] * inv; g4.y = val[1] * inv; g4.z = val[2] * inv; g4.w = val[3] * inv;
    *(float4*)(g_G + rowo) = g4;
}

// ---------------- LayerNorm: one warp/row, one-pass ----------------
__device__ __forceinline__ void ln_row(const float* __restrict__ in, float* __restrict__ out,
                                       const float* __restrict__ g, const float* __restrict__ bt,
                                       long row, int lane, int relu) {
    const float* p = in + row * DIM + lane * 8;
    float4 v0 = *(const float4*)p;
    float4 v1 = *(const float4*)(p + 4);
    float s = v0.x + v0.y + v0.z + v0.w + v1.x + v1.y + v1.z + v1.w;
    float q = v0.x * v0.x + v0.y * v0.y + v0.z * v0.z + v0.w * v0.w
            + v1.x * v1.x + v1.y * v1.y + v1.z * v1.z + v1.w * v1.w;
#pragma unroll
    for (int o = 16; o; o >>= 1) {
        s += __shfl_xor_sync(0xffffffffu, s, o);
        q += __shfl_xor_sync(0xffffffffu, q, o);
    }
    float mean = s * (1.0f / DIM);
    float var = q * (1.0f / DIM) - mean * mean;
    float rstd = rsqrtf(var + EPS);
    const float* gp = g + lane * 8;
    const float* bp = bt + lane * 8;
    float4 g0 = *(const float4*)gp, g1 = *(const float4*)(gp + 4);
    float4 b0 = *(const float4*)bp, b1 = *(const float4*)(bp + 4);
    float o8[8];
    o8[0] = (v0.x - mean) * rstd * g0.x + b0.x; o8[1] = (v0.y - mean) * rstd * g0.y + b0.y;
    o8[2] = (v0.z - mean) * rstd * g0.z + b0.z; o8[3] = (v0.w - mean) * rstd * g0.w + b0.w;
    o8[4] = (v1.x - mean) * rstd * g1.x + b1.x; o8[5] = (v1.y - mean) * rstd * g1.y + b1.y;
    o8[6] = (v1.z - mean) * rstd * g1.z + b1.z; o8[7] = (v1.w - mean) * rstd * g1.w + b1.w;
    if (relu) {
#pragma unroll
        for (int t = 0; t < 8; t++) o8[t] = fmaxf(o8[t], 0.0f);
    }
    float* po = out + row * DIM + lane * 8;
    float4 r0; r0.x = o8[0]; r0.y = o8[1]; r0.z = o8[2]; r0.w = o8[3];
    float4 r1; r1.x = o8[4]; r1.y = o8[5]; r1.z = o8[6]; r1.w = o8[7];
    *(float4*)po = r0;
    *(float4*)(po + 4) = r1;
}

__global__ __launch_bounds__(256)
void ln_one(const float* __restrict__ in, float* __restrict__ out,
            const float* __restrict__ g, const float* __restrict__ bt) {
    int w = threadIdx.x >> 5, lane = threadIdx.x & 31;
    ln_row(in, out, g, bt, (long)blockIdx.x * 8 + w, lane, 0);
}

__global__ __launch_bounds__(256)
void ln_fused(const float* __restrict__ inA, float* __restrict__ outA,
              const float* __restrict__ gA, const float* __restrict__ bA,
              const float* __restrict__ inB, float* __restrict__ outB,
              const float* __restrict__ gB, const float* __restrict__ bB, int nA) {
    int w = threadIdx.x >> 5, lane = threadIdx.x & 31;
    int bid = blockIdx.x;
    if (bid < nA)
        ln_row(inA, outA, gA, bA, (long)bid * 8 + w, lane, 1);
    else
        ln_row(inB, outB, gB, bB, (long)(bid - nA) * 8 + w, lane, 0);
}

// ---------------- host ----------------
extern "C" void kernel_launch(void* const* d_in, const int* in_sizes, int n_in,
                              void* d_out, int out_size) {
    const float* x_in   = (const float*)d_in[0];
    const float* abias  = (const float*)d_in[1];
    const float* ln1_g  = (const float*)d_in[2];
    const float* ln1_b  = (const float*)d_in[3];
    const float* Wkv    = (const float*)d_in[4];
    const float* Wq     = (const float*)d_in[5];
    const float* Wo     = (const float*)d_in[6];
    const float* bo     = (const float*)d_in[7];
    const float* ln2_g  = (const float*)d_in[8];
    const float* ln2_b  = (const float*)d_in[9];
    const float* W1     = (const float*)d_in[10];
    const float* b1     = (const float*)d_in[11];
    const float* W2     = (const float*)d_in[12];
    const float* b2     = (const float*)d_in[13];
    const float* Wg     = (const float*)d_in[14];
    const float* lng_g  = (const float*)d_in[15];
    const float* lng_b  = (const float*)d_in[16];
    float* out = (float*)d_out;

    float *px, *pxn, *pxma, *pq, *pkv, *pao, *pG, *pff;
    __half* pbias;
    cudaGetSymbolAddress((void**)&px, g_x);
    cudaGetSymbolAddress((void**)&pxn, g_xn);
    cudaGetSymbolAddress((void**)&pxma, g_xma);
    cudaGetSymbolAddress((void**)&pq, g_q);
    cudaGetSymbolAddress((void**)&pkv, g_kv);
    cudaGetSymbolAddress((void**)&pao, g_ao);
    cudaGetSymbolAddress((void**)&pG, g_G);
    cudaGetSymbolAddress((void**)&pbias, g_bias);
    cudaGetSymbolAddress((void**)&pff, g_ff);

    const int ROWS = BB * NN_;           // 4096
    const long ND = (long)NN_ * DIM;
    dim3 blk(256);

    const int SM_FL = (128 * 68 + 2 * 128 * 68 + 2 * 128 * 72) * 4;  // 178176
    cudaFuncSetAttribute(mma_gemm<0>, cudaFuncAttributeMaxDynamicSharedMemorySize, SM_G);
    cudaFuncSetAttribute(mma_gemm<2>, cudaFuncAttributeMaxDynamicSharedMemorySize, SM_G);
    cudaFuncSetAttribute(mma_gemm<3>, cudaFuncAttributeMaxDynamicSharedMemorySize, SM_G);
    cudaFuncSetAttribute(kvq_gemm, cudaFuncAttributeMaxDynamicSharedMemorySize, SM_G);
    cudaFuncSetAttribute(flash_kernel, cudaFuncAttributeMaxDynamicSharedMemorySize, SM_FL);

    prep_kernel<<<BB * NN_, blk>>>(abias);

    for (int l = 0; l < DEPTH; l++) {
        const float* xcur = (l == 0) ? x_in : px;
        // GX = G @ x -> g_xn   [per b: 1024x256, K=1024]
        mma_gemm<0><<<dim3(DIM / 64, NN_ / 128, BB), blk, SM_G>>>(
            pG, xcur, pxn, nullptr, nullptr,
            NN_, NN_, DIM, DIM, (long)NN_ * NN_, ND, ND);
        // x_ma_pre = GX @ Wg -> g_xma
        mma_gemm<0><<<dim3(DIM / 64, ROWS / 128, 1), blk, SM_G>>>(
            pxn, Wg, pxma, nullptr, nullptr,
            DIM, DIM, DIM, DIM, 0, 0, 0);
        // merged: x_ma = relu(LN(x_ma)) ; xn = LN(x)
        ln_fused<<<ROWS / 4, blk>>>(pxma, pxma, lng_g, lng_b,
                                    xcur, pxn, ln1_g + l * DIM, ln1_b + l * DIM, ROWS / 8);
        // merged kv + q (384 blocks)
        kvq_gemm<<<dim3(12, ROWS / 128, 1), blk, SM_G>>>(
            pxn, Wkv + (long)l * DIM * 2 * DIM, pkv,
            pxma, Wq + (long)l * DIM * DIM, pq);
        // fused attention -> g_ao
        flash_kernel<<<dim3(NN_ / 128, HEADS, BB), blk, SM_FL>>>(pq, pkv, pbias, pao);
        // x = x + out @ Wo[l] + bo[l]
        mma_gemm<2><<<dim3(DIM / 64, ROWS / 128, 1), blk, SM_G>>>(
            pao, Wo + (long)l * DIM * DIM, px, xcur, bo + l * DIM,
            DIM, DIM, DIM, DIM, 0, 0, 0);
        // xn2 = LN(x)
        ln_one<<<ROWS / 8, blk>>>(px, pxn, ln2_g + l * DIM, ln2_b + l * DIM);
        // ff = gelu(xn2 @ W1[l] + b1[l])  (512 blocks)
        mma_gemm<3><<<dim3(MLP / 64, ROWS / 128, 1), blk, SM_G>>>(
            pxn, W1 + (long)l * DIM * MLP, pff, nullptr, b1 + l * MLP,
            DIM, DIM, MLP, MLP, 0, 0, 0);
        // x = x + ff @ W2[l] + b2[l]  (last layer -> d_out)
        float* cdst = (l == DEPTH - 1) ? out : px;
        mma_gemm<2><<<dim3(DIM / 64, ROWS / 128, 1), blk, SM_G>>>(
            pff, W2 + (long)l * MLP * DIM, cdst, px, b2 + l * DIM,
            MLP, MLP, DIM, DIM, 0, 0, 0);
    }
}

// round 8
// speedup vs baseline: 1.6869x; 1.0661x over previous
#include <cuda_runtime.h>
#include <cuda_fp16.h>
#include <math.h>
#include <stdint.h>

#define BB 4
#define NN_ 1024
#define DIM 256
#define HEADS 4
#define DH 64
#define DEPTH 4
#define MLP 1024
#define EPS 1e-5f
#define SCALE 0.0625f   // DIM^-0.5

// ---------------- scratch ----------------
__device__ float g_x  [BB*NN_*DIM];
__device__ float g_xn [BB*NN_*DIM];
__device__ float g_xma[BB*NN_*DIM];
__device__ float g_q  [BB*NN_*DIM];
__device__ float g_kv [BB*NN_*2*DIM];
__device__ float g_ao [BB*NN_*DIM];
__device__ float g_G  [(long)BB*NN_*NN_];
__device__ __half g_bias[(long)BB*HEADS*NN_*NN_];
__device__ float g_ff [BB*NN_*MLP];

// ---------------- helpers ----------------
__device__ __forceinline__ float warp_sum(float v) {
#pragma unroll
    for (int o = 16; o; o >>= 1) v += __shfl_xor_sync(0xffffffffu, v, o);
    return v;
}
__device__ __forceinline__ float warp_max(float v) {
#pragma unroll
    for (int o = 16; o; o >>= 1) v = fmaxf(v, __shfl_xor_sync(0xffffffffu, v, o));
    return v;
}
__device__ __forceinline__ float block_sum(float v, float* sh) {
    int lane = threadIdx.x & 31, w = threadIdx.x >> 5;
    v = warp_sum(v);
    if (lane == 0) sh[w] = v;
    __syncthreads();
    v = (lane < 8) ? sh[lane] : 0.0f;
    v = warp_sum(v);
    __syncthreads();
    return v;
}
__device__ __forceinline__ float block_max(float v, float* sh) {
    int lane = threadIdx.x & 31, w = threadIdx.x >> 5;
    v = warp_max(v);
    if (lane == 0) sh[w] = v;
    __syncthreads();
    v = (lane < 8) ? sh[lane] : -INFINITY;
    v = warp_max(v);
    __syncthreads();
    return v;
}

__device__ __forceinline__ uint32_t f2tf(float f) {
    uint32_t u;
    asm("cvt.rna.tf32.f32 %0, %1;" : "=r"(u) : "f"(f));
    return u;
}
__device__ __forceinline__ uint32_t tfb(uint32_t bits) {
    return f2tf(__uint_as_float(bits));
}
__device__ __forceinline__ float pr(float f) {          // tf32-pre-round, keep as float
    return __uint_as_float(f2tf(f));
}
__device__ __forceinline__ void mma_tf32(float c[4], const uint32_t a[4], const uint32_t b[2]) {
    asm volatile(
        "mma.sync.aligned.m16n8k8.row.col.f32.tf32.tf32.f32 "
        "{%0,%1,%2,%3}, {%4,%5,%6,%7}, {%8,%9}, {%0,%1,%2,%3};"
        : "+f"(c[0]), "+f"(c[1]), "+f"(c[2]), "+f"(c[3])
        : "r"(a[0]), "r"(a[1]), "r"(a[2]), "r"(a[3]), "r"(b[0]), "r"(b[1]));
}
__device__ __forceinline__ uint32_t smem_u32(const void* p) {
    return (uint32_t)__cvta_generic_to_shared(p);
}
__device__ __forceinline__ void cpa16(uint32_t dst, const void* src) {
    asm volatile("cp.async.cg.shared.global [%0], [%1], 16;" :: "r"(dst), "l"(src));
}
__device__ __forceinline__ void cp_commit() { asm volatile("cp.async.commit_group;"); }
template <int N> __device__ __forceinline__ void cp_wait() {
    asm volatile("cp.async.wait_group %0;" :: "n"(N));
}

// ---------------- dense GEMM core: BM=128 BN=64 WM=32 WN=32 BK=32, 3-stage, 2 CTA/SM ------
// PRA: A operand already tf32-rounded (skip cvt). PROUT: round outputs to tf32.
#define LDA 36
#define LDB 72
#define STG 3
#define STAGE_WORDS (128 * LDA + 32 * LDB)
#define SM_G (STG * STAGE_WORDS * 4)

template <int EPI, bool PRA, bool PROUT>
__device__ __forceinline__ void gemm_core(
    const float* __restrict__ A, const float* __restrict__ Bm,
    float* __restrict__ C, const float* __restrict__ E, const float* __restrict__ bv,
    int K, int lda, int ldb, int ldc, int row0, int col0, uint32_t* smraw) {

    const int tid = threadIdx.x, wid = tid >> 5, lane = tid & 31;
    const int gid = lane >> 2, tg = lane & 3;
    const int wm0 = (wid >> 1) * 32, wn0 = (wid & 1) * 32;

    float acc[2][4][4];
#pragma unroll
    for (int i = 0; i < 2; i++)
#pragma unroll
        for (int j = 0; j < 4; j++)
#pragma unroll
            for (int k = 0; k < 4; k++) acc[i][j][k] = 0.0f;

    auto issue = [&](int buf, int t) {
        int k0 = t * 32;
        uint32_t as = smem_u32(smraw + buf * STAGE_WORDS);
        uint32_t bs = as + 128 * LDA * 4;
#pragma unroll
        for (int i = 0; i < 4; i++) {
            int q = tid + i * 256;
            int m = q >> 3, kq = q & 7;
            cpa16(as + (m * LDA + 4 * kq) * 4,
                  A + (long)(row0 + m) * lda + k0 + 4 * kq);
        }
#pragma unroll
        for (int i = 0; i < 2; i++) {
            int q = tid + i * 256;
            int kk = q >> 4, nq = q & 15;
            cpa16(bs + (kk * LDB + 4 * nq) * 4,
                  Bm + (long)(k0 + kk) * ldb + col0 + 4 * nq);
        }
        cp_commit();
    };
    auto compute = [&](int buf) {
        const uint32_t* ab = smraw + buf * STAGE_WORDS;
        const uint32_t* bb = ab + 128 * LDA;
#pragma unroll
        for (int ks = 0; ks < 32; ks += 8) {
            uint32_t af[2][4], bf[4][2];
#pragma unroll
            for (int mt = 0; mt < 2; mt++) {
                const uint32_t* p = ab + (wm0 + mt * 16 + gid) * LDA + ks + tg;
                if (PRA) {
                    af[mt][0] = p[0];
                    af[mt][1] = p[8 * LDA];
                    af[mt][2] = p[4];
                    af[mt][3] = p[8 * LDA + 4];
                } else {
                    af[mt][0] = tfb(p[0]);
                    af[mt][1] = tfb(p[8 * LDA]);
                    af[mt][2] = tfb(p[4]);
                    af[mt][3] = tfb(p[8 * LDA + 4]);
                }
            }
#pragma unroll
            for (int nt = 0; nt < 4; nt++) {
                const uint32_t* p = bb + (ks + tg) * LDB + wn0 + nt * 8 + gid;
                bf[nt][0] = tfb(p[0]);
                bf[nt][1] = tfb(p[4 * LDB]);
            }
#pragma unroll
            for (int mt = 0; mt < 2; mt++)
#pragma unroll
                for (int nt = 0; nt < 4; nt++)
                    mma_tf32(acc[mt][nt], af[mt], bf[nt]);
        }
    };

    const int TILES = K / 32;
    issue(0, 0);
    if (TILES > 1) issue(1, 1);
    else cp_commit();
    int buf = 0, nxt = 2;
    for (int t = 0; t < TILES; t++) {
        cp_wait<STG - 2>();
        __syncthreads();
        if (t + 2 < TILES) issue(nxt, t + 2);
        else cp_commit();
        compute(buf);
        buf = (buf + 1 == STG) ? 0 : buf + 1;
        nxt = (nxt + 1 == STG) ? 0 : nxt + 1;
        __syncthreads();
    }

#pragma unroll
    for (int mt = 0; mt < 2; mt++)
#pragma unroll
        for (int nt = 0; nt < 4; nt++)
#pragma unroll
            for (int half = 0; half < 2; half++) {
                int r = row0 + wm0 + mt * 16 + gid + half * 8;
                int c = col0 + wn0 + nt * 8 + 2 * tg;
                long off = (long)r * ldc + c;
                float v0 = acc[mt][nt][half * 2 + 0];
                float v1 = acc[mt][nt][half * 2 + 1];
                if (EPI == 2) {
                    float2 e = *(const float2*)(E + off);
                    v0 += e.x + bv[c];
                    v1 += e.y + bv[c + 1];
                } else if (EPI == 3) {
                    v0 += bv[c];
                    v1 += bv[c + 1];
                    v0 = 0.5f * v0 * (1.0f + erff(v0 * 0.70710678118654752f));
                    v1 = 0.5f * v1 * (1.0f + erff(v1 * 0.70710678118654752f));
                }
                if (PROUT) { v0 = pr(v0); v1 = pr(v1); }
                float2 o; o.x = v0; o.y = v1;
                *(float2*)(C + off) = o;
            }
}

template <int EPI, bool PRA, bool PROUT>
__global__ __launch_bounds__(256, 2)
void mma_gemm(const float* __restrict__ A, const float* __restrict__ Bm,
              float* __restrict__ C, const float* __restrict__ E,
              const float* __restrict__ bv,
              int K, int lda, int ldb, int ldc,
              long Ab, long Bb, long Cb) {
    extern __shared__ __align__(16) uint32_t smraw[];
    int z = blockIdx.z;
    A += (long)z * Ab;
    Bm += (long)z * Bb;
    long co = (long)z * Cb;
    gemm_core<EPI, PRA, PROUT>(A, Bm, C + co, (EPI == 2) ? E + co : E, bv,
                               K, lda, ldb, ldc, blockIdx.y * 128, blockIdx.x * 64, smraw);
}

// merged kv + q launch: blockIdx.x [0,8) -> kv (N=512), [8,12) -> q (N=256)
// A operands (xn/xma) are LN outputs, pre-rounded; outputs pre-rounded for flash.
__global__ __launch_bounds__(256, 2)
void kvq_gemm(const float* __restrict__ xn, const float* __restrict__ Wkv,
              float* __restrict__ kv,
              const float* __restrict__ xma, const float* __restrict__ Wq,
              float* __restrict__ qo) {
    extern __shared__ __align__(16) uint32_t smraw[];
    int row0 = blockIdx.y * 128;
    if (blockIdx.x < 8)
        gemm_core<0, true, true>(xn, Wkv, kv, nullptr, nullptr,
                                 DIM, DIM, 2 * DIM, 2 * DIM, row0, blockIdx.x * 64, smraw);
    else
        gemm_core<0, true, true>(xma, Wq, qo, nullptr, nullptr,
                                 DIM, DIM, DIM, DIM, row0, (blockIdx.x - 8) * 64, smraw);
}

// ---------------- fused flash attention ----------------
// Q/K/V inputs are tf32-pre-rounded -> no cvt in mainloop.
// No max tracking: logits bounded (|bias|<~8, |qk*scale|<~1); shift cancels in O = sum(pV)/sum(p).
__global__ __launch_bounds__(256)
void flash_kernel(const float* __restrict__ Qg, const float* __restrict__ KVg,
                  const __half* __restrict__ biasg, float* __restrict__ Og) {
    extern __shared__ uint32_t sm[];
    uint32_t* Qs = sm;                    // [128][68]
    uint32_t* Ks = Qs + 128 * 68;         // [2][128*68]
    uint32_t* Vs = Ks + 2 * 128 * 68;     // [2][128*72]

    const int i0 = blockIdx.x * 128;
    const int h = blockIdx.y, b = blockIdx.z;
    const float* Qp = Qg + (long)b * NN_ * DIM + h * DH;
    const float* Kp = KVg + (long)b * NN_ * 2 * DIM + h * DH;
    const float* Vp = Kp + DIM;
    const __half* Bp = biasg + ((long)(b * HEADS + h)) * NN_ * NN_ + (long)i0 * NN_;

    const int tid = threadIdx.x, wid = tid >> 5, lane = tid & 31;
    const int gid = lane >> 2, tg = lane & 3;
    const int wm0 = wid * 16;

    auto issue_kv = [&](int buf, int j0) {
        uint32_t ks = smem_u32(Ks + buf * 128 * 68);
        uint32_t vs = smem_u32(Vs + buf * 128 * 72);
#pragma unroll
        for (int t = 0; t < 8; t++) {
            int q = tid + t * 256;
            int n = q >> 4, c4 = (q & 15) << 2;
            cpa16(ks + (n * 68 + c4) * 4, Kp + (long)(j0 + n) * (2 * DIM) + c4);
            cpa16(vs + (n * 72 + c4) * 4, Vp + (long)(j0 + n) * (2 * DIM) + c4);
        }
        cp_commit();
    };

    issue_kv(0, 0);

    // Q tile: already tf32-rounded, raw copy
#pragma unroll
    for (int t = 0; t < 8; t++) {
        int q = tid + t * 256;
        int m = q >> 4, c4 = (q & 15) << 2;
        uint4 v = *(const uint4*)(Qp + (long)(i0 + m) * DIM + c4);
        *(uint4*)(Qs + m * 68 + c4) = v;
    }

    float oacc[8][4];
#pragma unroll
    for (int i = 0; i < 8; i++)
#pragma unroll
        for (int j = 0; j < 4; j++) oacc[i][j] = 0.0f;
    float li0 = 0.0f, li1 = 0.0f;          // per-thread partial row sums

    for (int t = 0; t < NN_ / 128; t++) {
        const int j0 = t * 128;
        const int buf = t & 1;
        cp_wait<0>();
        __syncthreads();
        if (t + 1 < NN_ / 128) issue_kv(buf ^ 1, j0 + 128);

        const uint32_t* kb = Ks + buf * 128 * 68;
        const uint32_t* vb = Vs + buf * 128 * 72;

        float s[16][4];
#pragma unroll
        for (int i = 0; i < 16; i++)
#pragma unroll
            for (int j = 0; j < 4; j++) s[i][j] = 0.0f;
#pragma unroll
        for (int ks = 0; ks < 64; ks += 8) {
            uint32_t a[4];
            const uint32_t* pa = Qs + (wm0 + gid) * 68 + ks + tg;
            a[0] = pa[0];
            a[1] = pa[8 * 68];
            a[2] = pa[4];
            a[3] = pa[8 * 68 + 4];
#pragma unroll
            for (int nt = 0; nt < 16; nt++) {
                const uint32_t* pb = kb + (nt * 8 + gid) * 68 + ks + tg;
                uint32_t bf[2] = { pb[0], pb[4] };
                mma_tf32(s[nt], a, bf);
            }
        }

        // bias + scale + exp (no shift), accumulate row sums
#pragma unroll
        for (int nt = 0; nt < 16; nt++) {
            long o0 = (long)(wm0 + gid) * NN_ + j0 + nt * 8 + 2 * tg;
            float2 e0 = __half22float2(*(const __half2*)(Bp + o0));
            float2 e1 = __half22float2(*(const __half2*)(Bp + o0 + 8 * NN_));
            s[nt][0] = __expf(fmaf(s[nt][0], SCALE, e0.x)); li0 += s[nt][0];
            s[nt][1] = __expf(fmaf(s[nt][1], SCALE, e0.y)); li0 += s[nt][1];
            s[nt][2] = __expf(fmaf(s[nt][2], SCALE, e1.x)); li1 += s[nt][2];
            s[nt][3] = __expf(fmaf(s[nt][3], SCALE, e1.y)); li1 += s[nt][3];
        }

        // P redistribute (C-frag -> A-frag) via shuffles, then O += P @ V
        const int src = (lane & ~3) | (tg >> 1);
        const bool odd = (tg & 1);
#pragma unroll
        for (int g = 0; g < 16; g++) {
            float f0 = __shfl_sync(0xffffffffu, s[g][0], src);
            float f1 = __shfl_sync(0xffffffffu, s[g][1], src);
            float f2 = __shfl_sync(0xffffffffu, s[g][0], src + 2);
            float f3 = __shfl_sync(0xffffffffu, s[g][1], src + 2);
            float h0 = __shfl_sync(0xffffffffu, s[g][2], src);
            float h1 = __shfl_sync(0xffffffffu, s[g][3], src);
            float h2 = __shfl_sync(0xffffffffu, s[g][2], src + 2);
            float h3 = __shfl_sync(0xffffffffu, s[g][3], src + 2);
            uint32_t pa4[4];
            pa4[0] = f2tf(odd ? f1 : f0);
            pa4[1] = f2tf(odd ? h1 : h0);
            pa4[2] = f2tf(odd ? f3 : f2);
            pa4[3] = f2tf(odd ? h3 : h2);
#pragma unroll
            for (int nt = 0; nt < 8; nt++) {
                const uint32_t* pb = vb + (g * 8 + tg) * 72 + nt * 8 + gid;
                uint32_t bf[2] = { pb[0], pb[4 * 72] };
                mma_tf32(oacc[nt], pa4, bf);
            }
        }
    }

    // one reduction at the end (rows owned by tg-groups of 4 lanes)
    li0 += __shfl_xor_sync(0xffffffffu, li0, 1);
    li0 += __shfl_xor_sync(0xffffffffu, li0, 2);
    li1 += __shfl_xor_sync(0xffffffffu, li1, 1);
    li1 += __shfl_xor_sync(0xffffffffu, li1, 2);
    float iv0 = 1.0f / li0, iv1 = 1.0f / li1;
#pragma unroll
    for (int nt = 0; nt < 8; nt++) {
        long off = ((long)b * NN_ + i0 + wm0 + gid) * DIM + h * DH + nt * 8 + 2 * tg;
        float2 o0; o0.x = pr(oacc[nt][0] * iv0); o0.y = pr(oacc[nt][1] * iv0);
        float2 o1; o1.x = pr(oacc[nt][2] * iv1); o1.y = pr(oacc[nt][3] * iv1);
        *(float2*)(Og + off) = o0;
        *(float2*)(Og + off + 8 * DIM) = o1;
    }
}

// ---------------- prep: add_attn(fp16) ; G = tf32(softmax(mean(b0)*mean(b1))) ----------
__global__ __launch_bounds__(256)
void prep_kernel(const float* __restrict__ ab) {
    __shared__ float sh[32];
    int b = blockIdx.x >> 10;
    int i = blockIdx.x & 1023;
    const long BHNN = (long)BB * HEADS * NN_ * NN_;
    int tid = threadIdx.x;
    int j4 = tid * 4;
    float4 sa = make_float4(0, 0, 0, 0), sb = make_float4(0, 0, 0, 0);
#pragma unroll
    for (int h = 0; h < HEADS; h++) {
        long o = (((long)(b * HEADS + h) * NN_) + i) * NN_ + j4;
        float4 a0 = *(const float4*)(ab + o);
        float4 a1 = *(const float4*)(ab + BHNN + o);
        sa.x += a0.x; sa.y += a0.y; sa.z += a0.z; sa.w += a0.w;
        sb.x += a1.x; sb.y += a1.y; sb.z += a1.z; sb.w += a1.w;
        union { __half2 h2[2]; uint2 u; } pk;
        pk.h2[0] = __floats2half2_rn(a0.x + a1.x, a0.y + a1.y);
        pk.h2[1] = __floats2half2_rn(a0.z + a1.z, a0.w + a1.w);
        *(uint2*)(&g_bias[o]) = pk.u;
    }
    float val[4];
    val[0] = (sa.x * 0.25f) * (sb.x * 0.25f);
    val[1] = (sa.y * 0.25f) * (sb.y * 0.25f);
    val[2] = (sa.z * 0.25f) * (sb.z * 0.25f);
    val[3] = (sa.w * 0.25f) * (sb.w * 0.25f);
    float m = fmaxf(fmaxf(val[0], val[1]), fmaxf(val[2], val[3]));
    m = block_max(m, sh);
    float s = 0.0f;
#pragma unroll
    for (int t = 0; t < 4; t++) { val[t] = __expf(val[t] - m); s += val[t]; }
    s = block_sum(s, sh);
    float inv = 1.0f / s;
    long rowo = ((long)(b * NN_ + i)) * NN_ + j4;
    float4 g4;
    g4.x = pr(val[0] * inv); g4.y = pr(val[1] * inv);
    g4.z = pr(val[2] * inv); g4.w = pr(val[3] * inv);
    *(float4*)(g_G + rowo) = g4;
}

// ---------------- LayerNorm: one warp/row, one-pass; outputs tf32-pre-rounded ----------------
__device__ __forceinline__ void ln_row(const float* __restrict__ in, float* __restrict__ out,
                                       const float* __restrict__ g, const float* __restrict__ bt,
                                       long row, int lane, int relu) {
    const float* p = in + row * DIM + lane * 8;
    float4 v0 = *(const float4*)p;
    float4 v1 = *(const float4*)(p + 4);
    float s = v0.x + v0.y + v0.z + v0.w + v1.x + v1.y + v1.z + v1.w;
    float q = v0.x * v0.x + v0.y * v0.y + v0.z * v0.z + v0.w * v0.w
            + v1.x * v1.x + v1.y * v1.y + v1.z * v1.z + v1.w * v1.w;
#pragma unroll
    for (int o = 16; o; o >>= 1) {
        s += __shfl_xor_sync(0xffffffffu, s, o);
        q += __shfl_xor_sync(0xffffffffu, q, o);
    }
    float mean = s * (1.0f / DIM);
    float var = q * (1.0f / DIM) - mean * mean;
    float rstd = rsqrtf(var + EPS);
    const float* gp = g + lane * 8;
    const float* bp = bt + lane * 8;
    float4 g0 = *(const float4*)gp, g1 = *(const float4*)(gp + 4);
    float4 b0 = *(const float4*)bp, b1 = *(const float4*)(bp + 4);
    float o8[8];
    o8[0] = (v0.x - mean) * rstd * g0.x + b0.x; o8[1] = (v0.y - mean) * rstd * g0.y + b0.y;
    o8[2] = (v0.z - mean) * rstd * g0.z + b0.z; o8[3] = (v0.w - mean) * rstd * g0.w + b0.w;
    o8[4] = (v1.x - mean) * rstd * g1.x + b1.x; o8[5] = (v1.y - mean) * rstd * g1.y + b1.y;
    o8[6] = (v1.z - mean) * rstd * g1.z + b1.z; o8[7] = (v1.w - mean) * rstd * g1.w + b1.w;
    if (relu) {
#pragma unroll
        for (int t = 0; t < 8; t++) o8[t] = fmaxf(o8[t], 0.0f);
    }
#pragma unroll
    for (int t = 0; t < 8; t++) o8[t] = pr(o8[t]);   // consumers are GEMM A-operands
    float* po = out + row * DIM + lane * 8;
    float4 r0; r0.x = o8[0]; r0.y = o8[1]; r0.z = o8[2]; r0.w = o8[3];
    float4 r1; r1.x = o8[4]; r1.y = o8[5]; r1.z = o8[6]; r1.w = o8[7];
    *(float4*)po = r0;
    *(float4*)(po + 4) = r1;
}

__global__ __launch_bounds__(256)
void ln_one(const float* __restrict__ in, float* __restrict__ out,
            const float* __restrict__ g, const float* __restrict__ bt) {
    int w = threadIdx.x >> 5, lane = threadIdx.x & 31;
    ln_row(in, out, g, bt, (long)blockIdx.x * 8 + w, lane, 0);
}

__global__ __launch_bounds__(256)
void ln_fused(const float* __restrict__ inA, float* __restrict__ outA,
              const float* __restrict__ gA, const float* __restrict__ bA,
              const float* __restrict__ inB, float* __restrict__ outB,
              const float* __restrict__ gB, const float* __restrict__ bB, int nA) {
    int w = threadIdx.x >> 5, lane = threadIdx.x & 31;
    int bid = blockIdx.x;
    if (bid < nA)
        ln_row(inA, outA, gA, bA, (long)bid * 8 + w, lane, 1);
    else
        ln_row(inB, outB, gB, bB, (long)(bid - nA) * 8 + w, lane, 0);
}

// ---------------- host ----------------
extern "C" void kernel_launch(void* const* d_in, const int* in_sizes, int n_in,
                              void* d_out, int out_size) {
    const float* x_in   = (const float*)d_in[0];
    const float* abias  = (const float*)d_in[1];
    const float* ln1_g  = (const float*)d_in[2];
    const float* ln1_b  = (const float*)d_in[3];
    const float* Wkv    = (const float*)d_in[4];
    const float* Wq     = (const float*)d_in[5];
    const float* Wo     = (const float*)d_in[6];
    const float* bo     = (const float*)d_in[7];
    const float* ln2_g  = (const float*)d_in[8];
    const float* ln2_b  = (const float*)d_in[9];
    const float* W1     = (const float*)d_in[10];
    const float* b1     = (const float*)d_in[11];
    const float* W2     = (const float*)d_in[12];
    const float* b2     = (const float*)d_in[13];
    const float* Wg     = (const float*)d_in[14];
    const float* lng_g  = (const float*)d_in[15];
    const float* lng_b  = (const float*)d_in[16];
    float* out = (float*)d_out;

    float *px, *pxn, *pxma, *pq, *pkv, *pao, *pG, *pff;
    __half* pbias;
    cudaGetSymbolAddress((void**)&px, g_x);
    cudaGetSymbolAddress((void**)&pxn, g_xn);
    cudaGetSymbolAddress((void**)&pxma, g_xma);
    cudaGetSymbolAddress((void**)&pq, g_q);
    cudaGetSymbolAddress((void**)&pkv, g_kv);
    cudaGetSymbolAddress((void**)&pao, g_ao);
    cudaGetSymbolAddress((void**)&pG, g_G);
    cudaGetSymbolAddress((void**)&pbias, g_bias);
    cudaGetSymbolAddress((void**)&pff, g_ff);

    const int ROWS = BB * NN_;           // 4096
    const long ND = (long)NN_ * DIM;
    dim3 blk(256);

    const int SM_FL = (128 * 68 + 2 * 128 * 68 + 2 * 128 * 72) * 4;  // 178176
    cudaFuncSetAttribute(mma_gemm<0, true, true>, cudaFuncAttributeMaxDynamicSharedMemorySize, SM_G);
    cudaFuncSetAttribute(mma_gemm<0, true, false>, cudaFuncAttributeMaxDynamicSharedMemorySize, SM_G);
    cudaFuncSetAttribute(mma_gemm<2, true, false>, cudaFuncAttributeMaxDynamicSharedMemorySize, SM_G);
    cudaFuncSetAttribute(mma_gemm<3, true, true>, cudaFuncAttributeMaxDynamicSharedMemorySize, SM_G);
    cudaFuncSetAttribute(kvq_gemm, cudaFuncAttributeMaxDynamicSharedMemorySize, SM_G);
    cudaFuncSetAttribute(flash_kernel, cudaFuncAttributeMaxDynamicSharedMemorySize, SM_FL);

    prep_kernel<<<BB * NN_, blk>>>(abias);

    for (int l = 0; l < DEPTH; l++) {
        const float* xcur = (l == 0) ? x_in : px;
        // GX = G @ x -> g_xn   [A=G pre-rounded; out feeds Wg-A -> round]
        mma_gemm<0, true, true><<<dim3(DIM / 64, NN_ / 128, BB), blk, SM_G>>>(
            pG, xcur, pxn, nullptr, nullptr,
            NN_, NN_, DIM, DIM, (long)NN_ * NN_, ND, ND);
        // x_ma_pre = GX @ Wg -> g_xma   [A=GX rounded; out feeds LN -> raw]
        mma_gemm<0, true, false><<<dim3(DIM / 64, ROWS / 128, 1), blk, SM_G>>>(
            pxn, Wg, pxma, nullptr, nullptr,
            DIM, DIM, DIM, DIM, 0, 0, 0);
        // merged: x_ma = relu(LN(x_ma)) ; xn = LN(x)   (outputs tf32-rounded)
        ln_fused<<<ROWS / 4, blk>>>(pxma, pxma, lng_g, lng_b,
                                    xcur, pxn, ln1_g + l * DIM, ln1_b + l * DIM, ROWS / 8);
        // merged kv + q (384 blocks; outputs tf32-rounded for flash)
        kvq_gemm<<<dim3(12, ROWS / 128, 1), blk, SM_G>>>(
            pxn, Wkv + (long)l * DIM * 2 * DIM, pkv,
            pxma, Wq + (long)l * DIM * DIM, pq);
        // fused attention -> g_ao (tf32-rounded for Wo-A)
        flash_kernel<<<dim3(NN_ / 128, HEADS, BB), blk, SM_FL>>>(pq, pkv, pbias, pao);
        // x = x + out @ Wo[l] + bo[l]   [A=ao rounded; residual out stays fp32]
        mma_gemm<2, true, false><<<dim3(DIM / 64, ROWS / 128, 1), blk, SM_G>>>(
            pao, Wo + (long)l * DIM * DIM, px, xcur, bo + l * DIM,
            DIM, DIM, DIM, DIM, 0, 0, 0);
        // xn2 = LN(x)  (rounded)
        ln_one<<<ROWS / 8, blk>>>(px, pxn, ln2_g + l * DIM, ln2_b + l * DIM);
        // ff = gelu(xn2 @ W1[l] + b1[l])  [A=xn2 rounded; out feeds W2-A -> round]
        mma_gemm<3, true, true><<<dim3(MLP / 64, ROWS / 128, 1), blk, SM_G>>>(
            pxn, W1 + (long)l * DIM * MLP, pff, nullptr, b1 + l * MLP,
            DIM, DIM, MLP, MLP, 0, 0, 0);
        // x = x + ff @ W2[l] + b2[l]   [A=ff rounded; last layer -> d_out]
        float* cdst = (l == DEPTH - 1) ? out : px;
        mma_gemm<2, true, false><<<dim3(DIM / 64, ROWS / 128, 1), blk, SM_G>>>(
            pff, W2 + (long)l * MLP * DIM, cdst, px, b2 + l * DIM,
            MLP, MLP, DIM, DIM, 0, 0, 0);
    }
}

// round 9
// speedup vs baseline: 1.8386x; 1.0899x over previous
#include <cuda_runtime.h>
#include <cuda_fp16.h>
#include <math.h>
#include <stdint.h>

#define BB 4
#define NN_ 1024
#define DIM 256
#define HEADS 4
#define DH 64
#define DEPTH 4
#define MLP 1024
#define EPS 1e-5f
#define SCALE 0.0625f   // DIM^-0.5

// ---------------- scratch ----------------
__device__ float g_x  [BB*NN_*DIM];
__device__ float g_xn [BB*NN_*DIM];
__device__ float g_xma[BB*NN_*DIM];
__device__ float g_ao [BB*NN_*DIM];
__device__ float g_G  [(long)BB*NN_*NN_];
__device__ __half g_bias[(long)BB*HEADS*NN_*NN_];
__device__ float g_ff [BB*NN_*MLP];
__device__ __half g_kh [BB*NN_*DIM];          // K fp16 [b][token][h*DH+d]
__device__ __half g_qh [BB*NN_*DIM];          // Q fp16 [b][token][h*DH+d]
__device__ __half g_vth[BB*DIM*NN_];          // V fp16 transposed [b][h*DH+d][token]
__device__ float g_wtf[3211264];              // tf32-pre-rounded weights

// weight offsets in g_wtf
#define OW_KV 0
#define OW_Q  524288
#define OW_O  786432
#define OW_1  1048576
#define OW_2  2097152
#define OW_G  3145728

// ---------------- helpers ----------------
__device__ __forceinline__ float warp_sum(float v) {
#pragma unroll
    for (int o = 16; o; o >>= 1) v += __shfl_xor_sync(0xffffffffu, v, o);
    return v;
}
__device__ __forceinline__ float warp_max(float v) {
#pragma unroll
    for (int o = 16; o; o >>= 1) v = fmaxf(v, __shfl_xor_sync(0xffffffffu, v, o));
    return v;
}
__device__ __forceinline__ float block_sum(float v, float* sh) {
    int lane = threadIdx.x & 31, w = threadIdx.x >> 5;
    v = warp_sum(v);
    if (lane == 0) sh[w] = v;
    __syncthreads();
    v = (lane < 8) ? sh[lane] : 0.0f;
    v = warp_sum(v);
    __syncthreads();
    return v;
}
__device__ __forceinline__ float block_max(float v, float* sh) {
    int lane = threadIdx.x & 31, w = threadIdx.x >> 5;
    v = warp_max(v);
    if (lane == 0) sh[w] = v;
    __syncthreads();
    v = (lane < 8) ? sh[lane] : -INFINITY;
    v = warp_max(v);
    __syncthreads();
    return v;
}

__device__ __forceinline__ uint32_t f2tf(float f) {
    uint32_t u;
    asm("cvt.rna.tf32.f32 %0, %1;" : "=r"(u) : "f"(f));
    return u;
}
__device__ __forceinline__ uint32_t tfb(uint32_t bits) {
    return f2tf(__uint_as_float(bits));
}
__device__ __forceinline__ float pr(float f) {
    return __uint_as_float(f2tf(f));
}
__device__ __forceinline__ uint32_t packh(float a, float b) {
    __half2 h = __floats2half2_rn(a, b);
    return *reinterpret_cast<uint32_t*>(&h);
}
__device__ __forceinline__ void mma_tf32(float c[4], const uint32_t a[4], const uint32_t b[2]) {
    asm volatile(
        "mma.sync.aligned.m16n8k8.row.col.f32.tf32.tf32.f32 "
        "{%0,%1,%2,%3}, {%4,%5,%6,%7}, {%8,%9}, {%0,%1,%2,%3};"
        : "+f"(c[0]), "+f"(c[1]), "+f"(c[2]), "+f"(c[3])
        : "r"(a[0]), "r"(a[1]), "r"(a[2]), "r"(a[3]), "r"(b[0]), "r"(b[1]));
}
__device__ __forceinline__ void mma_f16(float c[4], const uint32_t a[4], const uint32_t b[2]) {
    asm volatile(
        "mma.sync.aligned.m16n8k16.row.col.f32.f16.f16.f32 "
        "{%0,%1,%2,%3}, {%4,%5,%6,%7}, {%8,%9}, {%0,%1,%2,%3};"
        : "+f"(c[0]), "+f"(c[1]), "+f"(c[2]), "+f"(c[3])
        : "r"(a[0]), "r"(a[1]), "r"(a[2]), "r"(a[3]), "r"(b[0]), "r"(b[1]));
}
__device__ __forceinline__ uint32_t smem_u32(const void* p) {
    return (uint32_t)__cvta_generic_to_shared(p);
}
__device__ __forceinline__ void cpa16(uint32_t dst, const void* src) {
    asm volatile("cp.async.cg.shared.global [%0], [%1], 16;" :: "r"(dst), "l"(src));
}
__device__ __forceinline__ void cp_commit() { asm volatile("cp.async.commit_group;"); }
template <int N> __device__ __forceinline__ void cp_wait() {
    asm volatile("cp.async.wait_group %0;" :: "n"(N));
}

// ---------------- dense GEMM core: BM=128 BN=64, BK=32, 3-stage, 2 CTA/SM ----------------
// PRA/PRB: operand already tf32-rounded. PROUT: round fp32 outputs.
// EPI: 0 plain fp32, 2 residual+bias, 3 gelu+bias, 4 fp16 out, 5 fp16 transposed out (V).
#define LDA 36
#define LDB 72
#define STG 3
#define STAGE_WORDS (128 * LDA + 32 * LDB)
#define SM_G (STG * STAGE_WORDS * 4)

template <int EPI, bool PRA, bool PRB, bool PROUT>
__device__ __forceinline__ void gemm_core(
    const float* __restrict__ A, const float* __restrict__ Bm,
    float* __restrict__ C, const float* __restrict__ E, const float* __restrict__ bv,
    int K, int lda, int ldb, int ldc, int row0, int col0, uint32_t* smraw) {

    const int tid = threadIdx.x, wid = tid >> 5, lane = tid & 31;
    const int gid = lane >> 2, tg = lane & 3;
    const int wm0 = (wid >> 1) * 32, wn0 = (wid & 1) * 32;

    float acc[2][4][4];
#pragma unroll
    for (int i = 0; i < 2; i++)
#pragma unroll
        for (int j = 0; j < 4; j++)
#pragma unroll
            for (int k = 0; k < 4; k++) acc[i][j][k] = 0.0f;

    auto issue = [&](int buf, int t) {
        int k0 = t * 32;
        uint32_t as = smem_u32(smraw + buf * STAGE_WORDS);
        uint32_t bs = as + 128 * LDA * 4;
#pragma unroll
        for (int i = 0; i < 4; i++) {
            int q = tid + i * 256;
            int m = q >> 3, kq = q & 7;
            cpa16(as + (m * LDA + 4 * kq) * 4,
                  A + (long)(row0 + m) * lda + k0 + 4 * kq);
        }
#pragma unroll
        for (int i = 0; i < 2; i++) {
            int q = tid + i * 256;
            int kk = q >> 4, nq = q & 15;
            cpa16(bs + (kk * LDB + 4 * nq) * 4,
                  Bm + (long)(k0 + kk) * ldb + col0 + 4 * nq);
        }
        cp_commit();
    };
    auto compute = [&](int buf) {
        const uint32_t* ab = smraw + buf * STAGE_WORDS;
        const uint32_t* bb = ab + 128 * LDA;
#pragma unroll
        for (int ks = 0; ks < 32; ks += 8) {
            uint32_t af[2][4], bf[4][2];
#pragma unroll
            for (int mt = 0; mt < 2; mt++) {
                const uint32_t* p = ab + (wm0 + mt * 16 + gid) * LDA + ks + tg;
                if (PRA) {
                    af[mt][0] = p[0]; af[mt][1] = p[8 * LDA];
                    af[mt][2] = p[4]; af[mt][3] = p[8 * LDA + 4];
                } else {
                    af[mt][0] = tfb(p[0]); af[mt][1] = tfb(p[8 * LDA]);
                    af[mt][2] = tfb(p[4]); af[mt][3] = tfb(p[8 * LDA + 4]);
                }
            }
#pragma unroll
            for (int nt = 0; nt < 4; nt++) {
                const uint32_t* p = bb + (ks + tg) * LDB + wn0 + nt * 8 + gid;
                if (PRB) { bf[nt][0] = p[0]; bf[nt][1] = p[4 * LDB]; }
                else { bf[nt][0] = tfb(p[0]); bf[nt][1] = tfb(p[4 * LDB]); }
            }
#pragma unroll
            for (int mt = 0; mt < 2; mt++)
#pragma unroll
                for (int nt = 0; nt < 4; nt++)
                    mma_tf32(acc[mt][nt], af[mt], bf[nt]);
        }
    };

    const int TILES = K / 32;
    issue(0, 0);
    if (TILES > 1) issue(1, 1);
    else cp_commit();
    int buf = 0, nxt = 2;
    for (int t = 0; t < TILES; t++) {
        cp_wait<STG - 2>();
        __syncthreads();
        if (t + 2 < TILES) issue(nxt, t + 2);
        else cp_commit();
        compute(buf);
        buf = (buf + 1 == STG) ? 0 : buf + 1;
        nxt = (nxt + 1 == STG) ? 0 : nxt + 1;
        __syncthreads();
    }

#pragma unroll
    for (int mt = 0; mt < 2; mt++)
#pragma unroll
        for (int nt = 0; nt < 4; nt++)
#pragma unroll
            for (int half = 0; half < 2; half++) {
                int r = row0 + wm0 + mt * 16 + gid + half * 8;
                int c = col0 + wn0 + nt * 8 + 2 * tg;
                float v0 = acc[mt][nt][half * 2 + 0];
                float v1 = acc[mt][nt][half * 2 + 1];
                if (EPI == 4) {
                    *(__half2*)((__half*)C + (long)r * ldc + c) = __floats2half2_rn(v0, v1);
                } else if (EPI == 5) {
                    __half* H = (__half*)C;
                    int bb2 = r >> 10, rl = r & 1023;
                    H[((long)bb2 * DIM + c) * NN_ + rl] = __float2half_rn(v0);
                    H[((long)bb2 * DIM + c + 1) * NN_ + rl] = __float2half_rn(v1);
                } else {
                    long off = (long)r * ldc + c;
                    if (EPI == 2) {
                        float2 e = *(const float2*)(E + off);
                        v0 += e.x + bv[c];
                        v1 += e.y + bv[c + 1];
                    } else if (EPI == 3) {
                        v0 += bv[c];
                        v1 += bv[c + 1];
                        v0 = 0.5f * v0 * (1.0f + erff(v0 * 0.70710678118654752f));
                        v1 = 0.5f * v1 * (1.0f + erff(v1 * 0.70710678118654752f));
                    }
                    if (PROUT) { v0 = pr(v0); v1 = pr(v1); }
                    float2 o; o.x = v0; o.y = v1;
                    *(float2*)(C + off) = o;
                }
            }
}

template <int EPI, bool PRA, bool PRB, bool PROUT>
__global__ __launch_bounds__(256, 2)
void mma_gemm(const float* __restrict__ A, const float* __restrict__ Bm,
              float* __restrict__ C, const float* __restrict__ E,
              const float* __restrict__ bv,
              int K, int lda, int ldb, int ldc,
              long Ab, long Bb, long Cb) {
    extern __shared__ __align__(16) uint32_t smraw[];
    int z = blockIdx.z;
    A += (long)z * Ab;
    Bm += (long)z * Bb;
    long co = (long)z * Cb;
    gemm_core<EPI, PRA, PRB, PROUT>(A, Bm, C + co, (EPI == 2) ? E + co : E, bv,
                                    K, lda, ldb, ldc, blockIdx.y * 128, blockIdx.x * 64, smraw);
}

// merged kv + q: bx [0,4) -> K fp16; [4,8) -> V fp16 transposed; [8,12) -> Q fp16
__global__ __launch_bounds__(256, 2)
void kvq_gemm(const float* __restrict__ xn, const float* __restrict__ Wkv,
              const float* __restrict__ xma, const float* __restrict__ Wq) {
    extern __shared__ __align__(16) uint32_t smraw[];
    int row0 = blockIdx.y * 128;
    int bx = blockIdx.x;
    if (bx < 4)
        gemm_core<4, true, true, false>(xn, Wkv, (float*)g_kh, nullptr, nullptr,
                                        DIM, DIM, 2 * DIM, DIM, row0, bx * 64, smraw);
    else if (bx < 8)
        gemm_core<5, true, true, false>(xn, Wkv + 256, (float*)g_vth, nullptr, nullptr,
                                        DIM, DIM, 2 * DIM, 0, row0, (bx - 4) * 64, smraw);
    else
        gemm_core<4, true, true, false>(xma, Wq, (float*)g_qh, nullptr, nullptr,
                                        DIM, DIM, DIM, DIM, row0, (bx - 8) * 64, smraw);
}

// ---------------- fused flash attention, fp16 operands (m16n8k16) ----------------
// smem: Q[128][72]h + K[2][128][72]h + Vt[2][64][136]h = 90112 B
#define FL_SMEM ((128 * 72 + 2 * 128 * 72 + 2 * 64 * 136) * 2)

__global__ __launch_bounds__(256)
void flash_kernel(const __half* __restrict__ Qg, const __half* __restrict__ Kg,
                  const __half* __restrict__ Vtg, const __half* __restrict__ biasg,
                  float* __restrict__ Og) {
    extern __shared__ __align__(16) __half smh[];
    __half* Qs = smh;                       // [128][72]
    __half* Ks = Qs + 128 * 72;             // [2][128*72]
    __half* Vts = Ks + 2 * 128 * 72;        // [2][64*136]

    const int i0 = blockIdx.x * 128;
    const int h = blockIdx.y, b = blockIdx.z;
    const __half* Qp = Qg + (long)b * NN_ * DIM + h * DH;
    const __half* Kp = Kg + (long)b * NN_ * DIM + h * DH;
    const __half* Vtp = Vtg + ((long)b * DIM + h * DH) * NN_;
    const __half* Bp = biasg + ((long)(b * HEADS + h)) * NN_ * NN_ + (long)i0 * NN_;

    const int tid = threadIdx.x, wid = tid >> 5, lane = tid & 31;
    const int gid = lane >> 2, tg = lane & 3;
    const int wm0 = wid * 16;

    auto issue_kv = [&](int buf, int j0) {
        uint32_t ks = smem_u32(Ks + buf * 128 * 72);
        uint32_t vs = smem_u32(Vts + buf * 64 * 136);
#pragma unroll
        for (int t = 0; t < 4; t++) {
            int q = tid + t * 256;
            int n = q >> 3, c8 = q & 7;
            cpa16(ks + (n * 72 + c8 * 8) * 2, Kp + (long)(j0 + n) * DIM + c8 * 8);
        }
#pragma unroll
        for (int t = 0; t < 4; t++) {
            int q = tid + t * 256;
            int r = q >> 4, c16 = q & 15;
            cpa16(vs + (r * 136 + c16 * 8) * 2, Vtp + (long)r * NN_ + j0 + c16 * 8);
        }
        cp_commit();
    };

    issue_kv(0, 0);

    // Q tile: fp16 raw copy
#pragma unroll
    for (int t = 0; t < 4; t++) {
        int q = tid + t * 256;
        int m = q >> 3, c8 = q & 7;
        *(uint4*)(Qs + m * 72 + c8 * 8) = *(const uint4*)(Qp + (long)(i0 + m) * DIM + c8 * 8);
    }

    float oacc[8][4];
#pragma unroll
    for (int i = 0; i < 8; i++)
#pragma unroll
        for (int j = 0; j < 4; j++) oacc[i][j] = 0.0f;
    float li0 = 0.0f, li1 = 0.0f;

    for (int t = 0; t < NN_ / 128; t++) {
        const int j0 = t * 128;
        const int buf = t & 1;
        cp_wait<0>();
        __syncthreads();
        if (t + 1 < NN_ / 128) issue_kv(buf ^ 1, j0 + 128);

        const __half* kb = Ks + buf * 128 * 72;
        const __half* vb = Vts + buf * 64 * 136;

        // S = Q @ K^T  (fp16 k16: 4 k-steps x 16 n-groups)
        float s[16][4];
#pragma unroll
        for (int i = 0; i < 16; i++)
#pragma unroll
            for (int j = 0; j < 4; j++) s[i][j] = 0.0f;
#pragma unroll
        for (int ks = 0; ks < 64; ks += 16) {
            uint32_t a[4];
            const __half* pa = Qs + (wm0 + gid) * 72 + ks + 2 * tg;
            a[0] = *(const uint32_t*)pa;
            a[1] = *(const uint32_t*)(pa + 8 * 72);
            a[2] = *(const uint32_t*)(pa + 8);
            a[3] = *(const uint32_t*)(pa + 8 * 72 + 8);
#pragma unroll
            for (int nt = 0; nt < 16; nt++) {
                const __half* pb = kb + (nt * 8 + gid) * 72 + ks + 2 * tg;
                uint32_t bf[2] = { *(const uint32_t*)pb, *(const uint32_t*)(pb + 8) };
                mma_f16(s[nt], a, bf);
            }
        }

        // bias + scale + exp (no shift), accumulate row sums
#pragma unroll
        for (int nt = 0; nt < 16; nt++) {
            long o0 = (long)(wm0 + gid) * NN_ + j0 + nt * 8 + 2 * tg;
            float2 e0 = __half22float2(*(const __half2*)(Bp + o0));
            float2 e1 = __half22float2(*(const __half2*)(Bp + o0 + 8 * NN_));
            s[nt][0] = __expf(fmaf(s[nt][0], SCALE, e0.x)); li0 += s[nt][0];
            s[nt][1] = __expf(fmaf(s[nt][1], SCALE, e0.y)); li0 += s[nt][1];
            s[nt][2] = __expf(fmaf(s[nt][2], SCALE, e1.x)); li1 += s[nt][2];
            s[nt][3] = __expf(fmaf(s[nt][3], SCALE, e1.y)); li1 += s[nt][3];
        }

        // O += P @ V : C-frag pairs == fp16 A-frag (zero shuffles)
#pragma unroll
        for (int ge = 0; ge < 16; ge += 2) {
            uint32_t pa4[4];
            pa4[0] = packh(s[ge][0], s[ge][1]);
            pa4[1] = packh(s[ge][2], s[ge][3]);
            pa4[2] = packh(s[ge + 1][0], s[ge + 1][1]);
            pa4[3] = packh(s[ge + 1][2], s[ge + 1][3]);
            int k0 = ge * 8;
#pragma unroll
            for (int nt = 0; nt < 8; nt++) {
                const __half* pb = vb + (nt * 8 + gid) * 136 + k0 + 2 * tg;
                uint32_t bf[2] = { *(const uint32_t*)pb, *(const uint32_t*)(pb + 8) };
                mma_f16(oacc[nt], pa4, bf);
            }
        }
    }

    li0 += __shfl_xor_sync(0xffffffffu, li0, 1);
    li0 += __shfl_xor_sync(0xffffffffu, li0, 2);
    li1 += __shfl_xor_sync(0xffffffffu, li1, 1);
    li1 += __shfl_xor_sync(0xffffffffu, li1, 2);
    float iv0 = 1.0f / li0, iv1 = 1.0f / li1;
#pragma unroll
    for (int nt = 0; nt < 8; nt++) {
        long off = ((long)b * NN_ + i0 + wm0 + gid) * DIM + h * DH + nt * 8 + 2 * tg;
        float2 o0; o0.x = pr(oacc[nt][0] * iv0); o0.y = pr(oacc[nt][1] * iv0);
        float2 o1; o1.x = pr(oacc[nt][2] * iv1); o1.y = pr(oacc[nt][3] * iv1);
        *(float2*)(Og + off) = o0;
        *(float2*)(Og + off + 8 * DIM) = o1;
    }
}

// ---------------- weight pre-round (tf32) ----------------
__global__ __launch_bounds__(256)
void pr_copy(const float* __restrict__ src, float* __restrict__ dst, int n4) {
    int i = blockIdx.x * 256 + threadIdx.x;
    if (i < n4) {
        float4 v = *(const float4*)(src + i * 4);
        float4 o; o.x = pr(v.x); o.y = pr(v.y); o.z = pr(v.z); o.w = pr(v.w);
        *(float4*)(dst + i * 4) = o;
    }
}

// ---------------- prep: add_attn(fp16) ; G = tf32(softmax(mean(b0)*mean(b1))) ----------
__global__ __launch_bounds__(256)
void prep_kernel(const float* __restrict__ ab) {
    __shared__ float sh[32];
    int b = blockIdx.x >> 10;
    int i = blockIdx.x & 1023;
    const long BHNN = (long)BB * HEADS * NN_ * NN_;
    int tid = threadIdx.x;
    int j4 = tid * 4;
    float4 sa = make_float4(0, 0, 0, 0), sb = make_float4(0, 0, 0, 0);
#pragma unroll
    for (int h = 0; h < HEADS; h++) {
        long o = (((long)(b * HEADS + h) * NN_) + i) * NN_ + j4;
        float4 a0 = *(const float4*)(ab + o);
        float4 a1 = *(const float4*)(ab + BHNN + o);
        sa.x += a0.x; sa.y += a0.y; sa.z += a0.z; sa.w += a0.w;
        sb.x += a1.x; sb.y += a1.y; sb.z += a1.z; sb.w += a1.w;
        union { __half2 h2[2]; uint2 u; } pk;
        pk.h2[0] = __floats2half2_rn(a0.x + a1.x, a0.y + a1.y);
        pk.h2[1] = __floats2half2_rn(a0.z + a1.z, a0.w + a1.w);
        *(uint2*)(&g_bias[o]) = pk.u;
    }
    float val[4];
    val[0] = (sa.x * 0.25f) * (sb.x * 0.25f);
    val[1] = (sa.y * 0.25f) * (sb.y * 0.25f);
    val[2] = (sa.z * 0.25f) * (sb.z * 0.25f);
    val[3] = (sa.w * 0.25f) * (sb.w * 0.25f);
    float m = fmaxf(fmaxf(val[0], val[1]), fmaxf(val[2], val[3]));
    m = block_max(m, sh);
    float s = 0.0f;
#pragma unroll
    for (int t = 0; t < 4; t++) { val[t] = __expf(val[t] - m); s += val[t]; }
    s = block_sum(s, sh);
    float inv = 1.0f / s;
    long rowo = ((long)(b * NN_ + i)) * NN_ + j4;
    float4 g4;
    g4.x = pr(val[0] * inv); g4.y = pr(val[1] * inv);
    g4.z = pr(val[2] * inv); g4.w = pr(val[3] * inv);
    *(float4*)(g_G + rowo) = g4;
}

// ---------------- LayerNorm: one warp/row, one-pass; outputs tf32-pre-rounded ----------------
__device__ __forceinline__ void ln_row(const float* __restrict__ in, float* __restrict__ out,
                                       const float* __restrict__ g, const float* __restrict__ bt,
                                       long row, int lane, int relu) {
    const float* p = in + row * DIM + lane * 8;
    float4 v0 = *(const float4*)p;
    float4 v1 = *(const float4*)(p + 4);
    float s = v0.x + v0.y + v0.z + v0.w + v1.x + v1.y + v1.z + v1.w;
    float q = v0.x * v0.x + v0.y * v0.y + v0.z * v0.z + v0.w * v0.w
            + v1.x * v1.x + v1.y * v1.y + v1.z * v1.z + v1.w * v1.w;
#pragma unroll
    for (int o = 16; o; o >>= 1) {
        s += __shfl_xor_sync(0xffffffffu, s, o);
        q += __shfl_xor_sync(0xffffffffu, q, o);
    }
    float mean = s * (1.0f / DIM);
    float var = q * (1.0f / DIM) - mean * mean;
    float rstd = rsqrtf(var + EPS);
    const float* gp = g + lane * 8;
    const float* bp = bt + lane * 8;
    float4 g0 = *(const float4*)gp, g1 = *(const float4*)(gp + 4);
    float4 b0 = *(const float4*)bp, b1 = *(const float4*)(bp + 4);
    float o8[8];
    o8[0] = (v0.x - mean) * rstd * g0.x + b0.x; o8[1] = (v0.y - mean) * rstd * g0.y + b0.y;
    o8[2] = (v0.z - mean) * rstd * g0.z + b0.z; o8[3] = (v0.w - mean) * rstd * g0.w + b0.w;
    o8[4] = (v1.x - mean) * rstd * g1.x + b1.x; o8[5] = (v1.y - mean) * rstd * g1.y + b1.y;
    o8[6] = (v1.z - mean) * rstd * g1.z + b1.z; o8[7] = (v1.w - mean) * rstd * g1.w + b1.w;
    if (relu) {
#pragma unroll
        for (int t = 0; t < 8; t++) o8[t] = fmaxf(o8[t], 0.0f);
    }
#pragma unroll
    for (int t = 0; t < 8; t++) o8[t] = pr(o8[t]);
    float* po = out + row * DIM + lane * 8;
    float4 r0; r0.x = o8[0]; r0.y = o8[1]; r0.z = o8[2]; r0.w = o8[3];
    float4 r1; r1.x = o8[4]; r1.y = o8[5]; r1.z = o8[6]; r1.w = o8[7];
    *(float4*)po = r0;
    *(float4*)(po + 4) = r1;
}

__global__ __launch_bounds__(256)
void ln_one(const float* __restrict__ in, float* __restrict__ out,
            const float* __restrict__ g, const float* __restrict__ bt) {
    int w = threadIdx.x >> 5, lane = threadIdx.x & 31;
    ln_row(in, out, g, bt, (long)blockIdx.x * 8 + w, lane, 0);
}

__global__ __launch_bounds__(256)
void ln_fused(const float* __restrict__ inA, float* __restrict__ outA,
              const float* __restrict__ gA, const float* __restrict__ bA,
              const float* __restrict__ inB, float* __restrict__ outB,
              const float* __restrict__ gB, const float* __restrict__ bB, int nA) {
    int w = threadIdx.x >> 5, lane = threadIdx.x & 31;
    int bid = blockIdx.x;
    if (bid < nA)
        ln_row(inA, outA, gA, bA, (long)bid * 8 + w, lane, 1);
    else
        ln_row(inB, outB, gB, bB, (long)(bid - nA) * 8 + w, lane, 0);
}

// ---------------- host ----------------
extern "C" void kernel_launch(void* const* d_in, const int* in_sizes, int n_in,
                              void* d_out, int out_size) {
    const float* x_in   = (const float*)d_in[0];
    const float* abias  = (const float*)d_in[1];
    const float* ln1_g  = (const float*)d_in[2];
    const float* ln1_b  = (const float*)d_in[3];
    const float* Wkv    = (const float*)d_in[4];
    const float* Wq     = (const float*)d_in[5];
    const float* Wo     = (const float*)d_in[6];
    const float* bo     = (const float*)d_in[7];
    const float* ln2_g  = (const float*)d_in[8];
    const float* ln2_b  = (const float*)d_in[9];
    const float* W1     = (const float*)d_in[10];
    const float* b1     = (const float*)d_in[11];
    const float* W2     = (const float*)d_in[12];
    const float* b2     = (const float*)d_in[13];
    const float* Wg     = (const float*)d_in[14];
    const float* lng_g  = (const float*)d_in[15];
    const float* lng_b  = (const float*)d_in[16];
    float* out = (float*)d_out;

    float *px, *pxn, *pxma, *pao, *pG, *pff, *pwtf;
    __half *pbias, *pkh, *pqh, *pvth;
    cudaGetSymbolAddress((void**)&px, g_x);
    cudaGetSymbolAddress((void**)&pxn, g_xn);
    cudaGetSymbolAddress((void**)&pxma, g_xma);
    cudaGetSymbolAddress((void**)&pao, g_ao);
    cudaGetSymbolAddress((void**)&pG, g_G);
    cudaGetSymbolAddress((void**)&pbias, g_bias);
    cudaGetSymbolAddress((void**)&pff, g_ff);
    cudaGetSymbolAddress((void**)&pwtf, g_wtf);
    cudaGetSymbolAddress((void**)&pkh, g_kh);
    cudaGetSymbolAddress((void**)&pqh, g_qh);
    cudaGetSymbolAddress((void**)&pvth, g_vth);

    const int ROWS = BB * NN_;           // 4096
    const long ND = (long)NN_ * DIM;
    dim3 blk(256);

    cudaFuncSetAttribute(mma_gemm<0, true, false, true>, cudaFuncAttributeMaxDynamicSharedMemorySize, SM_G);
    cudaFuncSetAttribute(mma_gemm<0, true, true, false>, cudaFuncAttributeMaxDynamicSharedMemorySize, SM_G);
    cudaFuncSetAttribute(mma_gemm<2, true, true, false>, cudaFuncAttributeMaxDynamicSharedMemorySize, SM_G);
    cudaFuncSetAttribute(mma_gemm<3, true, true, true>, cudaFuncAttributeMaxDynamicSharedMemorySize, SM_G);
    cudaFuncSetAttribute(kvq_gemm, cudaFuncAttributeMaxDynamicSharedMemorySize, SM_G);
    cudaFuncSetAttribute(flash_kernel, cudaFuncAttributeMaxDynamicSharedMemorySize, FL_SMEM);

    // weight pre-round (runs per replay; ~13MB r/w)
    pr_copy<<<(524288 / 4 + 255) / 256, blk>>>(Wkv, pwtf + OW_KV, 524288 / 4);
    pr_copy<<<(262144 / 4 + 255) / 256, blk>>>(Wq, pwtf + OW_Q, 262144 / 4);
    pr_copy<<<(262144 / 4 + 255) / 256, blk>>>(Wo, pwtf + OW_O, 262144 / 4);
    pr_copy<<<(1048576 / 4 + 255) / 256, blk>>>(W1, pwtf + OW_1, 1048576 / 4);
    pr_copy<<<(1048576 / 4 + 255) / 256, blk>>>(W2, pwtf + OW_2, 1048576 / 4);
    pr_copy<<<(65536 / 4 + 255) / 256, blk>>>(Wg, pwtf + OW_G, 65536 / 4);

    prep_kernel<<<BB * NN_, blk>>>(abias);

    for (int l = 0; l < DEPTH; l++) {
        const float* xcur = (l == 0) ? x_in : px;
        // GX = G @ x -> g_xn  [B = live fp32 x: PRB=false]
        mma_gemm<0, true, false, true><<<dim3(DIM / 64, NN_ / 128, BB), blk, SM_G>>>(
            pG, xcur, pxn, nullptr, nullptr,
            NN_, NN_, DIM, DIM, (long)NN_ * NN_, ND, ND);
        // x_ma_pre = GX @ Wg -> g_xma
        mma_gemm<0, true, true, false><<<dim3(DIM / 64, ROWS / 128, 1), blk, SM_G>>>(
            pxn, pwtf + OW_G, pxma, nullptr, nullptr,
            DIM, DIM, DIM, DIM, 0, 0, 0);
        // merged: x_ma = relu(LN(x_ma)) ; xn = LN(x)
        ln_fused<<<ROWS / 4, blk>>>(pxma, pxma, lng_g, lng_b,
                                    xcur, pxn, ln1_g + l * DIM, ln1_b + l * DIM, ROWS / 8);
        // merged K/V/Q -> fp16 (V transposed)
        kvq_gemm<<<dim3(12, ROWS / 128, 1), blk, SM_G>>>(
            pxn, pwtf + OW_KV + (long)l * DIM * 2 * DIM,
            pxma, pwtf + OW_Q + (long)l * DIM * DIM);
        // fused fp16 attention -> g_ao
        flash_kernel<<<dim3(NN_ / 128, HEADS, BB), blk, FL_SMEM>>>(pqh, pkh, pvth, pbias, pao);
        // x = x + out @ Wo[l] + bo[l]
        mma_gemm<2, true, true, false><<<dim3(DIM / 64, ROWS / 128, 1), blk, SM_G>>>(
            pao, pwtf + OW_O + (long)l * DIM * DIM, px, xcur, bo + l * DIM,
            DIM, DIM, DIM, DIM, 0, 0, 0);
        // xn2 = LN(x)
        ln_one<<<ROWS / 8, blk>>>(px, pxn, ln2_g + l * DIM, ln2_b + l * DIM);
        // ff = gelu(xn2 @ W1[l] + b1[l])
        mma_gemm<3, true, true, true><<<dim3(MLP / 64, ROWS / 128, 1), blk, SM_G>>>(
            pxn, pwtf + OW_1 + (long)l * DIM * MLP, pff, nullptr, b1 + l * MLP,
            DIM, DIM, MLP, MLP, 0, 0, 0);
        // x = x + ff @ W2[l] + b2[l]  (last layer -> d_out)
        float* cdst = (l == DEPTH - 1) ? out : px;
        mma_gemm<2, true, true, false><<<dim3(DIM / 64, ROWS / 128, 1), blk, SM_G>>>(
            pff, pwtf + OW_2 + (long)l * MLP * DIM, cdst, px, b2 + l * DIM,
            MLP, MLP, DIM, DIM, 0, 0, 0);
    }
}

// round 10
// speedup vs baseline: 2.3391x; 1.2722x over previous
#include <cuda_runtime.h>
#include <cuda_fp16.h>
#include <math.h>
#include <stdint.h>

#define BB 4
#define NN_ 1024
#define DIM 256
#define HEADS 4
#define DH 64
#define DEPTH 4
#define MLP 1024
#define EPS 1e-5f
#define SCALE 0.0625f   // DIM^-0.5

// ---------------- scratch ----------------
__device__ float  g_x   [BB*NN_*DIM];            // residual (fp32)
__device__ float  g_xma [BB*NN_*DIM];            // Wg out (fp32, LN input)
__device__ __half g_Gh  [(long)BB*NN_*NN_];      // G fp16
__device__ __half g_bias[(long)BB*HEADS*NN_*NN_];
__device__ __half g_xnh [BB*NN_*DIM];            // LN(x) / LN2(x) fp16
__device__ __half g_xmah[BB*NN_*DIM];            // relu(LN(xma)) fp16
__device__ __half g_gxh [BB*NN_*DIM];            // GX fp16
__device__ __half g_aoh [BB*NN_*DIM];            // attention out fp16
__device__ __half g_ffh [BB*NN_*MLP];            // gelu out fp16
__device__ __half g_xth [BB*DIM*NN_];            // x^T fp16 (GX B operand)
__device__ __half g_kh  [BB*NN_*DIM];
__device__ __half g_qh  [BB*NN_*DIM];
__device__ __half g_vth [BB*DIM*NN_];
__device__ __half g_wh  [3211264];               // transposed fp16 weights

// weight offsets in g_wh (halves)
#define OW_KV 0
#define OW_Q  524288
#define OW_O  786432
#define OW_1  1048576
#define OW_2  2097152
#define OW_G  3145728

// ---------------- helpers ----------------
__device__ __forceinline__ float warp_sum(float v) {
#pragma unroll
    for (int o = 16; o; o >>= 1) v += __shfl_xor_sync(0xffffffffu, v, o);
    return v;
}
__device__ __forceinline__ float warp_max(float v) {
#pragma unroll
    for (int o = 16; o; o >>= 1) v = fmaxf(v, __shfl_xor_sync(0xffffffffu, v, o));
    return v;
}
__device__ __forceinline__ float block_sum(float v, float* sh) {
    int lane = threadIdx.x & 31, w = threadIdx.x >> 5;
    v = warp_sum(v);
    if (lane == 0) sh[w] = v;
    __syncthreads();
    v = (lane < 8) ? sh[lane] : 0.0f;
    v = warp_sum(v);
    __syncthreads();
    return v;
}
__device__ __forceinline__ float block_max(float v, float* sh) {
    int lane = threadIdx.x & 31, w = threadIdx.x >> 5;
    v = warp_max(v);
    if (lane == 0) sh[w] = v;
    __syncthreads();
    v = (lane < 8) ? sh[lane] : -INFINITY;
    v = warp_max(v);
    __syncthreads();
    return v;
}
__device__ __forceinline__ uint32_t packh(float a, float b) {
    __half2 h = __floats2half2_rn(a, b);
    return *reinterpret_cast<uint32_t*>(&h);
}
__device__ __forceinline__ void mma_f16(float c[4], const uint32_t a[4], const uint32_t b[2]) {
    asm volatile(
        "mma.sync.aligned.m16n8k16.row.col.f32.f16.f16.f32 "
        "{%0,%1,%2,%3}, {%4,%5,%6,%7}, {%8,%9}, {%0,%1,%2,%3};"
        : "+f"(c[0]), "+f"(c[1]), "+f"(c[2]), "+f"(c[3])
        : "r"(a[0]), "r"(a[1]), "r"(a[2]), "r"(a[3]), "r"(b[0]), "r"(b[1]));
}
__device__ __forceinline__ uint32_t smem_u32(const void* p) {
    return (uint32_t)__cvta_generic_to_shared(p);
}
__device__ __forceinline__ void cpa16(uint32_t dst, const void* src) {
    asm volatile("cp.async.cg.shared.global [%0], [%1], 16;" :: "r"(dst), "l"(src));
}
__device__ __forceinline__ void cp_commit() { asm volatile("cp.async.commit_group;"); }
template <int N> __device__ __forceinline__ void cp_wait() {
    asm volatile("cp.async.wait_group %0;" :: "n"(N));
}

// ---------------- fp16 dense GEMM: BM=128 BN=64 BK=32, m16n8k16, 3-stage, 3 CTA/SM --------
// A fp16 [M][K] row-major; Bt fp16 [N][K] (transposed weights / x^T).
// EPI: 0 fp32 out, 2 residual+bias fp32, 3 gelu->fp16, 4 fp16 out, 5 fp16 transposed (V),
//      6 residual+bias fp32 + fp16 transposed copy (x^T for next layer).
#define LAH 40
#define LBH 40
#define STGH 3
#define STAGE_H (128 * LAH + 64 * LBH)      // halves = 7680 (15360 B)
#define SM_GH (STGH * STAGE_H * 2)          // 46080 B

template <int EPI>
__device__ __forceinline__ void gemm_core_h(
    const __half* __restrict__ A, const __half* __restrict__ Bt,
    void* __restrict__ Cv, const float* __restrict__ E, const float* __restrict__ bv,
    __half* __restrict__ H2,
    int K, int lda, int ldb, int ldc, int row0, int col0, __half* smh) {

    const int tid = threadIdx.x, wid = tid >> 5, lane = tid & 31;
    const int gid = lane >> 2, tg = lane & 3;
    const int wm0 = (wid >> 1) * 32, wn0 = (wid & 1) * 32;

    float acc[2][4][4];
#pragma unroll
    for (int i = 0; i < 2; i++)
#pragma unroll
        for (int j = 0; j < 4; j++)
#pragma unroll
            for (int k = 0; k < 4; k++) acc[i][j][k] = 0.0f;

    auto issue = [&](int buf, int t) {
        int k0 = t * 32;
        uint32_t as = smem_u32(smh + buf * STAGE_H);
        uint32_t bs = as + 128 * LAH * 2;
#pragma unroll
        for (int i = 0; i < 2; i++) {
            int q = tid + i * 256;
            int m = q >> 2, c16 = q & 3;
            cpa16(as + (m * LAH + c16 * 8) * 2,
                  A + (long)(row0 + m) * lda + k0 + c16 * 8);
        }
        {
            int n = tid >> 2, c16 = tid & 3;
            cpa16(bs + (n * LBH + c16 * 8) * 2,
                  Bt + (long)(col0 + n) * ldb + k0 + c16 * 8);
        }
        cp_commit();
    };
    auto compute = [&](int buf) {
        const __half* ab = smh + buf * STAGE_H;
        const __half* bb = ab + 128 * LAH;
#pragma unroll
        for (int ks = 0; ks < 32; ks += 16) {
            uint32_t af[2][4], bf[4][2];
#pragma unroll
            for (int mt = 0; mt < 2; mt++) {
                const __half* p = ab + (wm0 + mt * 16 + gid) * LAH + ks + 2 * tg;
                af[mt][0] = *(const uint32_t*)p;
                af[mt][1] = *(const uint32_t*)(p + 8 * LAH);
                af[mt][2] = *(const uint32_t*)(p + 8);
                af[mt][3] = *(const uint32_t*)(p + 8 * LAH + 8);
            }
#pragma unroll
            for (int nt = 0; nt < 4; nt++) {
                const __half* p = bb + (wn0 + nt * 8 + gid) * LBH + ks + 2 * tg;
                bf[nt][0] = *(const uint32_t*)p;
                bf[nt][1] = *(const uint32_t*)(p + 8);
            }
#pragma unroll
            for (int mt = 0; mt < 2; mt++)
#pragma unroll
                for (int nt = 0; nt < 4; nt++)
                    mma_f16(acc[mt][nt], af[mt], bf[nt]);
        }
    };

    const int TILES = K / 32;
    issue(0, 0);
    if (TILES > 1) issue(1, 1);
    else cp_commit();
    int buf = 0, nxt = 2;
    for (int t = 0; t < TILES; t++) {
        cp_wait<STGH - 2>();
        __syncthreads();
        if (t + 2 < TILES) issue(nxt, t + 2);
        else cp_commit();
        compute(buf);
        buf = (buf + 1 == STGH) ? 0 : buf + 1;
        nxt = (nxt + 1 == STGH) ? 0 : nxt + 1;
        __syncthreads();
    }

#pragma unroll
    for (int mt = 0; mt < 2; mt++)
#pragma unroll
        for (int nt = 0; nt < 4; nt++)
#pragma unroll
            for (int half = 0; half < 2; half++) {
                int r = row0 + wm0 + mt * 16 + gid + half * 8;
                int c = col0 + wn0 + nt * 8 + 2 * tg;
                float v0 = acc[mt][nt][half * 2 + 0];
                float v1 = acc[mt][nt][half * 2 + 1];
                if (EPI == 4) {
                    *(__half2*)((__half*)Cv + (long)r * ldc + c) = __floats2half2_rn(v0, v1);
                } else if (EPI == 5) {
                    __half* H = (__half*)Cv;
                    int bb2 = r >> 10, rl = r & 1023;
                    H[((long)bb2 * DIM + c) * NN_ + rl] = __float2half_rn(v0);
                    H[((long)bb2 * DIM + c + 1) * NN_ + rl] = __float2half_rn(v1);
                } else if (EPI == 3) {
                    v0 += bv[c];
                    v1 += bv[c + 1];
                    v0 = 0.5f * v0 * (1.0f + erff(v0 * 0.70710678118654752f));
                    v1 = 0.5f * v1 * (1.0f + erff(v1 * 0.70710678118654752f));
                    *(__half2*)((__half*)Cv + (long)r * ldc + c) = __floats2half2_rn(v0, v1);
                } else {
                    long off = (long)r * ldc + c;
                    if (EPI == 2 || EPI == 6) {
                        float2 e = *(const float2*)(E + off);
                        v0 += e.x + bv[c];
                        v1 += e.y + bv[c + 1];
                    }
                    float2 o; o.x = v0; o.y = v1;
                    *(float2*)((float*)Cv + off) = o;
                    if (EPI == 6) {
                        int bb2 = r >> 10, rl = r & 1023;
                        H2[((long)bb2 * DIM + c) * NN_ + rl] = __float2half_rn(v0);
                        H2[((long)bb2 * DIM + c + 1) * NN_ + rl] = __float2half_rn(v1);
                    }
                }
            }
}

template <int EPI>
__global__ __launch_bounds__(256, 3)
void mma_gemm_h(const __half* __restrict__ A, const __half* __restrict__ Bt,
                void* __restrict__ C, const float* __restrict__ E,
                const float* __restrict__ bv, __half* __restrict__ H2,
                int K, int lda, int ldb, int ldc,
                long Ab, long Bb, long Cb) {
    extern __shared__ __align__(16) __half smh[];
    int z = blockIdx.z;
    A += (long)z * Ab;
    Bt += (long)z * Bb;
    void* Cz = (EPI == 3 || EPI == 4 || EPI == 5)
               ? (void*)((__half*)C + (long)z * Cb)
               : (void*)((float*)C + (long)z * Cb);
    gemm_core_h<EPI>(A, Bt, Cz, E, bv, H2,
                     K, lda, ldb, ldc, blockIdx.y * 128, blockIdx.x * 64, smh);
}

// merged kv + q: bx [0,4) -> K fp16; [4,8) -> V fp16 transposed; [8,12) -> Q fp16
__global__ __launch_bounds__(256, 3)
void kvq_gemm(const __half* __restrict__ xn, const __half* __restrict__ Wkvt,
              const __half* __restrict__ xma, const __half* __restrict__ Wqt) {
    extern __shared__ __align__(16) __half smh[];
    int row0 = blockIdx.y * 128;
    int bx = blockIdx.x;
    if (bx < 4)
        gemm_core_h<4>(xn, Wkvt, (void*)g_kh, nullptr, nullptr, nullptr,
                       DIM, DIM, DIM, DIM, row0, bx * 64, smh);
    else if (bx < 8)
        gemm_core_h<5>(xn, Wkvt + 256 * DIM, (void*)g_vth, nullptr, nullptr, nullptr,
                       DIM, DIM, DIM, 0, row0, (bx - 4) * 64, smh);
    else
        gemm_core_h<4>(xma, Wqt, (void*)g_qh, nullptr, nullptr, nullptr,
                       DIM, DIM, DIM, DIM, row0, (bx - 8) * 64, smh);
}

// ---------------- fused flash attention, fp16 operands (m16n8k16) ----------------
#define FL_SMEM ((128 * 72 + 2 * 128 * 72 + 2 * 64 * 136) * 2)

__global__ __launch_bounds__(256)
void flash_kernel(const __half* __restrict__ Qg, const __half* __restrict__ Kg,
                  const __half* __restrict__ Vtg, const __half* __restrict__ biasg,
                  __half* __restrict__ Og) {
    extern __shared__ __align__(16) __half smh[];
    __half* Qs = smh;
    __half* Ks = Qs + 128 * 72;
    __half* Vts = Ks + 2 * 128 * 72;

    const int i0 = blockIdx.x * 128;
    const int h = blockIdx.y, b = blockIdx.z;
    const __half* Qp = Qg + (long)b * NN_ * DIM + h * DH;
    const __half* Kp = Kg + (long)b * NN_ * DIM + h * DH;
    const __half* Vtp = Vtg + ((long)b * DIM + h * DH) * NN_;
    const __half* Bp = biasg + ((long)(b * HEADS + h)) * NN_ * NN_ + (long)i0 * NN_;

    const int tid = threadIdx.x, wid = tid >> 5, lane = tid & 31;
    const int gid = lane >> 2, tg = lane & 3;
    const int wm0 = wid * 16;

    auto issue_kv = [&](int buf, int j0) {
        uint32_t ks = smem_u32(Ks + buf * 128 * 72);
        uint32_t vs = smem_u32(Vts + buf * 64 * 136);
#pragma unroll
        for (int t = 0; t < 4; t++) {
            int q = tid + t * 256;
            int n = q >> 3, c8 = q & 7;
            cpa16(ks + (n * 72 + c8 * 8) * 2, Kp + (long)(j0 + n) * DIM + c8 * 8);
        }
#pragma unroll
        for (int t = 0; t < 4; t++) {
            int q = tid + t * 256;
            int r = q >> 4, c16 = q & 15;
            cpa16(vs + (r * 136 + c16 * 8) * 2, Vtp + (long)r * NN_ + j0 + c16 * 8);
        }
        cp_commit();
    };

    issue_kv(0, 0);

#pragma unroll
    for (int t = 0; t < 4; t++) {
        int q = tid + t * 256;
        int m = q >> 3, c8 = q & 7;
        *(uint4*)(Qs + m * 72 + c8 * 8) = *(const uint4*)(Qp + (long)(i0 + m) * DIM + c8 * 8);
    }

    float oacc[8][4];
#pragma unroll
    for (int i = 0; i < 8; i++)
#pragma unroll
        for (int j = 0; j < 4; j++) oacc[i][j] = 0.0f;
    float li0 = 0.0f, li1 = 0.0f;

    for (int t = 0; t < NN_ / 128; t++) {
        const int j0 = t * 128;
        const int buf = t & 1;
        cp_wait<0>();
        __syncthreads();
        if (t + 1 < NN_ / 128) issue_kv(buf ^ 1, j0 + 128);

        const __half* kb = Ks + buf * 128 * 72;
        const __half* vb = Vts + buf * 64 * 136;

        float s[16][4];
#pragma unroll
        for (int i = 0; i < 16; i++)
#pragma unroll
            for (int j = 0; j < 4; j++) s[i][j] = 0.0f;
#pragma unroll
        for (int ks = 0; ks < 64; ks += 16) {
            uint32_t a[4];
            const __half* pa = Qs + (wm0 + gid) * 72 + ks + 2 * tg;
            a[0] = *(const uint32_t*)pa;
            a[1] = *(const uint32_t*)(pa + 8 * 72);
            a[2] = *(const uint32_t*)(pa + 8);
            a[3] = *(const uint32_t*)(pa + 8 * 72 + 8);
#pragma unroll
            for (int nt = 0; nt < 16; nt++) {
                const __half* pb = kb + (nt * 8 + gid) * 72 + ks + 2 * tg;
                uint32_t bf[2] = { *(const uint32_t*)pb, *(const uint32_t*)(pb + 8) };
                mma_f16(s[nt], a, bf);
            }
        }

#pragma unroll
        for (int nt = 0; nt < 16; nt++) {
            long o0 = (long)(wm0 + gid) * NN_ + j0 + nt * 8 + 2 * tg;
            float2 e0 = __half22float2(*(const __half2*)(Bp + o0));
            float2 e1 = __half22float2(*(const __half2*)(Bp + o0 + 8 * NN_));
            s[nt][0] = __expf(fmaf(s[nt][0], SCALE, e0.x)); li0 += s[nt][0];
            s[nt][1] = __expf(fmaf(s[nt][1], SCALE, e0.y)); li0 += s[nt][1];
            s[nt][2] = __expf(fmaf(s[nt][2], SCALE, e1.x)); li1 += s[nt][2];
            s[nt][3] = __expf(fmaf(s[nt][3], SCALE, e1.y)); li1 += s[nt][3];
        }

#pragma unroll
        for (int ge = 0; ge < 16; ge += 2) {
            uint32_t pa4[4];
            pa4[0] = packh(s[ge][0], s[ge][1]);
            pa4[1] = packh(s[ge][2], s[ge][3]);
            pa4[2] = packh(s[ge + 1][0], s[ge + 1][1]);
            pa4[3] = packh(s[ge + 1][2], s[ge + 1][3]);
            int k0 = ge * 8;
#pragma unroll
            for (int nt = 0; nt < 8; nt++) {
                const __half* pb = vb + (nt * 8 + gid) * 136 + k0 + 2 * tg;
                uint32_t bf[2] = { *(const uint32_t*)pb, *(const uint32_t*)(pb + 8) };
                mma_f16(oacc[nt], pa4, bf);
            }
        }
    }

    li0 += __shfl_xor_sync(0xffffffffu, li0, 1);
    li0 += __shfl_xor_sync(0xffffffffu, li0, 2);
    li1 += __shfl_xor_sync(0xffffffffu, li1, 1);
    li1 += __shfl_xor_sync(0xffffffffu, li1, 2);
    float iv0 = 1.0f / li0, iv1 = 1.0f / li1;
#pragma unroll
    for (int nt = 0; nt < 8; nt++) {
        long off = ((long)b * NN_ + i0 + wm0 + gid) * DIM + h * DH + nt * 8 + 2 * tg;
        *(__half2*)(Og + off) = __floats2half2_rn(oacc[nt][0] * iv0, oacc[nt][1] * iv0);
        *(__half2*)(Og + off + 8 * DIM) = __floats2half2_rn(oacc[nt][2] * iv1, oacc[nt][3] * iv1);
    }
}

// ---------------- tiled transpose fp32 -> fp16: src [z][K][N] -> dst [z][N][K] ----------
__global__ void wtrans(const float* __restrict__ src, __half* __restrict__ dst,
                       int K, int N) {
    __shared__ float tile[32][33];
    int z = blockIdx.z;
    src += (long)z * K * N;
    dst += (long)z * K * N;
    int n0 = blockIdx.x * 32, k0 = blockIdx.y * 32;
    int tx = threadIdx.x, ty = threadIdx.y;
#pragma unroll
    for (int i = 0; i < 32; i += 8)
        tile[ty + i][tx] = src[(long)(k0 + ty + i) * N + n0 + tx];
    __syncthreads();
#pragma unroll
    for (int i = 0; i < 32; i += 8)
        dst[(long)(n0 + ty + i) * K + k0 + tx] = __float2half_rn(tile[tx][ty + i]);
}

// ---------------- prep: add_attn(fp16) ; G = fp16(softmax(mean(b0)*mean(b1))) ----------
__global__ __launch_bounds__(256)
void prep_kernel(const float* __restrict__ ab) {
    __shared__ float sh[32];
    int b = blockIdx.x >> 10;
    int i = blockIdx.x & 1023;
    const long BHNN = (long)BB * HEADS * NN_ * NN_;
    int tid = threadIdx.x;
    int j4 = tid * 4;
    float4 sa = make_float4(0, 0, 0, 0), sb = make_float4(0, 0, 0, 0);
#pragma unroll
    for (int h = 0; h < HEADS; h++) {
        long o = (((long)(b * HEADS + h) * NN_) + i) * NN_ + j4;
        float4 a0 = *(const float4*)(ab + o);
        float4 a1 = *(const float4*)(ab + BHNN + o);
        sa.x += a0.x; sa.y += a0.y; sa.z += a0.z; sa.w += a0.w;
        sb.x += a1.x; sb.y += a1.y; sb.z += a1.z; sb.w += a1.w;
        union { __half2 h2[2]; uint2 u; } pk;
        pk.h2[0] = __floats2half2_rn(a0.x + a1.x, a0.y + a1.y);
        pk.h2[1] = __floats2half2_rn(a0.z + a1.z, a0.w + a1.w);
        *(uint2*)(&g_bias[o]) = pk.u;
    }
    float val[4];
    val[0] = (sa.x * 0.25f) * (sb.x * 0.25f);
    val[1] = (sa.y * 0.25f) * (sb.y * 0.25f);
    val[2] = (sa.z * 0.25f) * (sb.z * 0.25f);
    val[3] = (sa.w * 0.25f) * (sb.w * 0.25f);
    float m = fmaxf(fmaxf(val[0], val[1]), fmaxf(val[2], val[3]));
    m = block_max(m, sh);
    float s = 0.0f;
#pragma unroll
    for (int t = 0; t < 4; t++) { val[t] = __expf(val[t] - m); s += val[t]; }
    s = block_sum(s, sh);
    float inv = 1.0f / s;
    long rowo = ((long)(b * NN_ + i)) * NN_ + j4;
    union { __half2 h2[2]; uint2 u; } gk;
    gk.h2[0] = __floats2half2_rn(val[0] * inv, val[1] * inv);
    gk.h2[1] = __floats2half2_rn(val[2] * inv, val[3] * inv);
    *(uint2*)(&g_Gh[rowo]) = gk.u;
}

// ---------------- LayerNorm: one warp/row, one-pass; fp16 output ----------------
__device__ __forceinline__ void ln_row(const float* __restrict__ in, __half* __restrict__ out,
                                       const float* __restrict__ g, const float* __restrict__ bt,
                                       long row, int lane, int relu) {
    const float* p = in + row * DIM + lane * 8;
    float4 v0 = *(const float4*)p;
    float4 v1 = *(const float4*)(p + 4);
    float s = v0.x + v0.y + v0.z + v0.w + v1.x + v1.y + v1.z + v1.w;
    float q = v0.x * v0.x + v0.y * v0.y + v0.z * v0.z + v0.w * v0.w
            + v1.x * v1.x + v1.y * v1.y + v1.z * v1.z + v1.w * v1.w;
#pragma unroll
    for (int o = 16; o; o >>= 1) {
        s += __shfl_xor_sync(0xffffffffu, s, o);
        q += __shfl_xor_sync(0xffffffffu, q, o);
    }
    float mean = s * (1.0f / DIM);
    float var = q * (1.0f / DIM) - mean * mean;
    float rstd = rsqrtf(var + EPS);
    const float* gp = g + lane * 8;
    const float* bp = bt + lane * 8;
    float4 g0 = *(const float4*)gp, g1 = *(const float4*)(gp + 4);
    float4 b0 = *(const float4*)bp, b1 = *(const float4*)(bp + 4);
    float o8[8];
    o8[0] = (v0.x - mean) * rstd * g0.x + b0.x; o8[1] = (v0.y - mean) * rstd * g0.y + b0.y;
    o8[2] = (v0.z - mean) * rstd * g0.z + b0.z; o8[3] = (v0.w - mean) * rstd * g0.w + b0.w;
    o8[4] = (v1.x - mean) * rstd * g1.x + b1.x; o8[5] = (v1.y - mean) * rstd * g1.y + b1.y;
    o8[6] = (v1.z - mean) * rstd * g1.z + b1.z; o8[7] = (v1.w - mean) * rstd * g1.w + b1.w;
    if (relu) {
#pragma unroll
        for (int t = 0; t < 8; t++) o8[t] = fmaxf(o8[t], 0.0f);
    }
    union { __half2 h2[4]; uint4 u; } pk;
    pk.h2[0] = __floats2half2_rn(o8[0], o8[1]);
    pk.h2[1] = __floats2half2_rn(o8[2], o8[3]);
    pk.h2[2] = __floats2half2_rn(o8[4], o8[5]);
    pk.h2[3] = __floats2half2_rn(o8[6], o8[7]);
    *(uint4*)(out + row * DIM + lane * 8) = pk.u;
}

__global__ __launch_bounds__(256)
void ln_one(const float* __restrict__ in, __half* __restrict__ out,
            const float* __restrict__ g, const float* __restrict__ bt) {
    int w = threadIdx.x >> 5, lane = threadIdx.x & 31;
    ln_row(in, out, g, bt, (long)blockIdx.x * 8 + w, lane, 0);
}

__global__ __launch_bounds__(256)
void ln_fused(const float* __restrict__ inA, __half* __restrict__ outA,
              const float* __restrict__ gA, const float* __restrict__ bA,
              const float* __restrict__ inB, __half* __restrict__ outB,
              const float* __restrict__ gB, const float* __restrict__ bB, int nA) {
    int w = threadIdx.x >> 5, lane = threadIdx.x & 31;
    int bid = blockIdx.x;
    if (bid < nA)
        ln_row(inA, outA, gA, bA, (long)bid * 8 + w, lane, 1);
    else
        ln_row(inB, outB, gB, bB, (long)(bid - nA) * 8 + w, lane, 0);
}

// ---------------- host ----------------
extern "C" void kernel_launch(void* const* d_in, const int* in_sizes, int n_in,
                              void* d_out, int out_size) {
    const float* x_in   = (const float*)d_in[0];
    const float* abias  = (const float*)d_in[1];
    const float* ln1_g  = (const float*)d_in[2];
    const float* ln1_b  = (const float*)d_in[3];
    const float* Wkv    = (const float*)d_in[4];
    const float* Wq     = (const float*)d_in[5];
    const float* Wo     = (const float*)d_in[6];
    const float* bo     = (const float*)d_in[7];
    const float* ln2_g  = (const float*)d_in[8];
    const float* ln2_b  = (const float*)d_in[9];
    const float* W1     = (const float*)d_in[10];
    const float* b1     = (const float*)d_in[11];
    const float* W2     = (const float*)d_in[12];
    const float* b2     = (const float*)d_in[13];
    const float* Wg     = (const float*)d_in[14];
    const float* lng_g  = (const float*)d_in[15];
    const float* lng_b  = (const float*)d_in[16];
    float* out = (float*)d_out;

    float *px, *pxma;
    __half *pGh, *pbias, *pxnh, *pxmah, *pgxh, *paoh, *pffh, *pxth, *pkh, *pqh, *pvth, *pwh;
    cudaGetSymbolAddress((void**)&px, g_x);
    cudaGetSymbolAddress((void**)&pxma, g_xma);
    cudaGetSymbolAddress((void**)&pGh, g_Gh);
    cudaGetSymbolAddress((void**)&pbias, g_bias);
    cudaGetSymbolAddress((void**)&pxnh, g_xnh);
    cudaGetSymbolAddress((void**)&pxmah, g_xmah);
    cudaGetSymbolAddress((void**)&pgxh, g_gxh);
    cudaGetSymbolAddress((void**)&paoh, g_aoh);
    cudaGetSymbolAddress((void**)&pffh, g_ffh);
    cudaGetSymbolAddress((void**)&pxth, g_xth);
    cudaGetSymbolAddress((void**)&pkh, g_kh);
    cudaGetSymbolAddress((void**)&pqh, g_qh);
    cudaGetSymbolAddress((void**)&pvth, g_vth);
    cudaGetSymbolAddress((void**)&pwh, g_wh);

    const int ROWS = BB * NN_;           // 4096
    const long ND = (long)NN_ * DIM;
    dim3 blk(256);
    dim3 tblk(32, 8);

    cudaFuncSetAttribute(mma_gemm_h<0>, cudaFuncAttributeMaxDynamicSharedMemorySize, SM_GH);
    cudaFuncSetAttribute(mma_gemm_h<2>, cudaFuncAttributeMaxDynamicSharedMemorySize, SM_GH);
    cudaFuncSetAttribute(mma_gemm_h<3>, cudaFuncAttributeMaxDynamicSharedMemorySize, SM_GH);
    cudaFuncSetAttribute(mma_gemm_h<4>, cudaFuncAttributeMaxDynamicSharedMemorySize, SM_GH);
    cudaFuncSetAttribute(mma_gemm_h<6>, cudaFuncAttributeMaxDynamicSharedMemorySize, SM_GH);
    cudaFuncSetAttribute(kvq_gemm, cudaFuncAttributeMaxDynamicSharedMemorySize, SM_GH);
    cudaFuncSetAttribute(flash_kernel, cudaFuncAttributeMaxDynamicSharedMemorySize, FL_SMEM);

    // weight transposes (fp32 -> fp16, [K][N] -> [N][K])
    wtrans<<<dim3(512 / 32, 256 / 32, DEPTH), tblk>>>(Wkv, pwh + OW_KV, 256, 512);
    wtrans<<<dim3(256 / 32, 256 / 32, DEPTH), tblk>>>(Wq, pwh + OW_Q, 256, 256);
    wtrans<<<dim3(256 / 32, 256 / 32, DEPTH), tblk>>>(Wo, pwh + OW_O, 256, 256);
    wtrans<<<dim3(1024 / 32, 256 / 32, DEPTH), tblk>>>(W1, pwh + OW_1, 256, 1024);
    wtrans<<<dim3(256 / 32, 1024 / 32, DEPTH), tblk>>>(W2, pwh + OW_2, 1024, 256);
    wtrans<<<dim3(256 / 32, 256 / 32, 1), tblk>>>(Wg, pwh + OW_G, 256, 256);
    // x_in -> x^T fp16 (layer 0 GX B operand)
    wtrans<<<dim3(256 / 32, 1024 / 32, BB), tblk>>>(x_in, pxth, 1024, 256);

    prep_kernel<<<BB * NN_, blk>>>(abias);

    for (int l = 0; l < DEPTH; l++) {
        const float* xcur = (l == 0) ? x_in : px;
        // GX = G @ x -> gxh fp16   [A=Gh, B=x^T fp16; per batch]
        mma_gemm_h<4><<<dim3(DIM / 64, NN_ / 128, BB), blk, SM_GH>>>(
            pGh, pxth, pgxh, nullptr, nullptr, nullptr,
            NN_, NN_, NN_, DIM, (long)NN_ * NN_, (long)DIM * NN_, ND);
        // x_ma_pre = GX @ Wg -> g_xma fp32
        mma_gemm_h<0><<<dim3(DIM / 64, ROWS / 128, 1), blk, SM_GH>>>(
            pgxh, pwh + OW_G, pxma, nullptr, nullptr, nullptr,
            DIM, DIM, DIM, DIM, 0, 0, 0);
        // merged: xmah = relu(LN(xma)) ; xnh = LN(x)
        ln_fused<<<ROWS / 4, blk>>>(pxma, pxmah, lng_g, lng_b,
                                    xcur, pxnh, ln1_g + l * DIM, ln1_b + l * DIM, ROWS / 8);
        // merged K/V/Q -> fp16 (V transposed)
        kvq_gemm<<<dim3(12, ROWS / 128, 1), blk, SM_GH>>>(
            pxnh, pwh + OW_KV + (long)l * 512 * DIM,
            pxmah, pwh + OW_Q + (long)l * DIM * DIM);
        // fused fp16 attention -> aoh
        flash_kernel<<<dim3(NN_ / 128, HEADS, BB), blk, FL_SMEM>>>(pqh, pkh, pvth, pbias, paoh);
        // x = x + ao @ Wo[l] + bo[l]
        mma_gemm_h<2><<<dim3(DIM / 64, ROWS / 128, 1), blk, SM_GH>>>(
            paoh, pwh + OW_O + (long)l * DIM * DIM, px, xcur, bo + l * DIM, nullptr,
            DIM, DIM, DIM, DIM, 0, 0, 0);
        // xn2 = LN(x) -> xnh
        ln_one<<<ROWS / 8, blk>>>(px, pxnh, ln2_g + l * DIM, ln2_b + l * DIM);
        // ff = gelu(xn2 @ W1[l] + b1[l]) -> ffh fp16
        mma_gemm_h<3><<<dim3(MLP / 64, ROWS / 128, 1), blk, SM_GH>>>(
            pxnh, pwh + OW_1 + (long)l * MLP * DIM, pffh, nullptr, b1 + l * MLP, nullptr,
            DIM, DIM, DIM, MLP, 0, 0, 0);
        // x = x + ff @ W2[l] + b2[l]; also write x^T fp16 for next GX (not last layer)
        if (l == DEPTH - 1) {
            mma_gemm_h<2><<<dim3(DIM / 64, ROWS / 128, 1), blk, SM_GH>>>(
                pffh, pwh + OW_2 + (long)l * DIM * MLP, out, px, b2 + l * DIM, nullptr,
                MLP, MLP, MLP, DIM, 0, 0, 0);
        } else {
            mma_gemm_h<6><<<dim3(DIM / 64, ROWS / 128, 1), blk, SM_GH>>>(
                pffh, pwh + OW_2 + (long)l * DIM * MLP, px, px, b2 + l * DIM, pxth,
                MLP, MLP, MLP, DIM, 0, 0, 0);
        }
    }
}

// round 11
// speedup vs baseline: 2.5874x; 1.1062x over previous
#include <cuda_runtime.h>
#include <cuda_fp16.h>
#include <math.h>
#include <stdint.h>

#define BB 4
#define NN_ 1024
#define DIM 256
#define HEADS 4
#define DH 64
#define DEPTH 4
#define MLP 1024
#define EPS 1e-5f
#define SCALE 0.0625f   // DIM^-0.5

// ---------------- scratch ----------------
__device__ float  g_x   [BB*NN_*DIM];            // residual (fp32)
__device__ float  g_xma [BB*NN_*DIM];            // Wg out (fp32, LN input)
__device__ __half g_Gh  [(long)BB*NN_*NN_];      // G fp16
__device__ __half g_bias[(long)BB*HEADS*NN_*NN_];
__device__ __half g_xnh [BB*NN_*DIM];            // LN(x) / LN2(x) fp16
__device__ __half g_xmah[BB*NN_*DIM];            // relu(LN(xma)) fp16
__device__ __half g_gxh [BB*NN_*DIM];            // GX fp16
__device__ __half g_aoh [BB*NN_*DIM];            // attention out fp16
__device__ __half g_ffh [BB*NN_*MLP];            // gelu out fp16
__device__ __half g_xth [BB*DIM*NN_];            // x^T fp16 (GX B operand)
__device__ __half g_kh  [BB*NN_*DIM];
__device__ __half g_qh  [BB*NN_*DIM];
__device__ __half g_vth [BB*DIM*NN_];
__device__ __half g_wh  [3211264];               // transposed fp16 weights

// weight offsets in g_wh (halves)
#define OW_KV 0
#define OW_Q  524288
#define OW_O  786432
#define OW_1  1048576
#define OW_2  2097152
#define OW_G  3145728

// ---------------- helpers ----------------
__device__ __forceinline__ float warp_sum(float v) {
#pragma unroll
    for (int o = 16; o; o >>= 1) v += __shfl_xor_sync(0xffffffffu, v, o);
    return v;
}
__device__ __forceinline__ float warp_max(float v) {
#pragma unroll
    for (int o = 16; o; o >>= 1) v = fmaxf(v, __shfl_xor_sync(0xffffffffu, v, o));
    return v;
}
__device__ __forceinline__ float block_sum(float v, float* sh) {
    int lane = threadIdx.x & 31, w = threadIdx.x >> 5;
    v = warp_sum(v);
    if (lane == 0) sh[w] = v;
    __syncthreads();
    v = (lane < 8) ? sh[lane] : 0.0f;
    v = warp_sum(v);
    __syncthreads();
    return v;
}
__device__ __forceinline__ float block_max(float v, float* sh) {
    int lane = threadIdx.x & 31, w = threadIdx.x >> 5;
    v = warp_max(v);
    if (lane == 0) sh[w] = v;
    __syncthreads();
    v = (lane < 8) ? sh[lane] : -INFINITY;
    v = warp_max(v);
    __syncthreads();
    return v;
}
__device__ __forceinline__ uint32_t packh(float a, float b) {
    __half2 h = __floats2half2_rn(a, b);
    return *reinterpret_cast<uint32_t*>(&h);
}
__device__ __forceinline__ void mma_f16(float c[4], const uint32_t a[4], const uint32_t b[2]) {
    asm volatile(
        "mma.sync.aligned.m16n8k16.row.col.f32.f16.f16.f32 "
        "{%0,%1,%2,%3}, {%4,%5,%6,%7}, {%8,%9}, {%0,%1,%2,%3};"
        : "+f"(c[0]), "+f"(c[1]), "+f"(c[2]), "+f"(c[3])
        : "r"(a[0]), "r"(a[1]), "r"(a[2]), "r"(a[3]), "r"(b[0]), "r"(b[1]));
}
__device__ __forceinline__ uint32_t smem_u32(const void* p) {
    return (uint32_t)__cvta_generic_to_shared(p);
}
__device__ __forceinline__ void cpa16(uint32_t dst, const void* src) {
    asm volatile("cp.async.cg.shared.global [%0], [%1], 16;" :: "r"(dst), "l"(src));
}
__device__ __forceinline__ void cp_commit() { asm volatile("cp.async.commit_group;"); }
template <int N> __device__ __forceinline__ void cp_wait() {
    asm volatile("cp.async.wait_group %0;" :: "n"(N));
}

// ---------------- fp16 dense GEMM: BM=128 BN=64 BK=32, m16n8k16, 4-stage, 3 CTA/SM --------
#define LAH 40
#define LBH 40
#define STGH 4
#define STAGE_H (128 * LAH + 64 * LBH)      // halves = 7680 (15360 B)
#define SM_GH (STGH * STAGE_H * 2)          // 61440 B

template <int EPI>
__device__ __forceinline__ void gemm_core_h(
    const __half* __restrict__ A, const __half* __restrict__ Bt,
    void* __restrict__ Cv, const float* __restrict__ E, const float* __restrict__ bv,
    __half* __restrict__ H2,
    int K, int lda, int ldb, int ldc, int row0, int col0, __half* smh) {

    const int tid = threadIdx.x, wid = tid >> 5, lane = tid & 31;
    const int gid = lane >> 2, tg = lane & 3;
    const int wm0 = (wid >> 1) * 32, wn0 = (wid & 1) * 32;

    float acc[2][4][4];
#pragma unroll
    for (int i = 0; i < 2; i++)
#pragma unroll
        for (int j = 0; j < 4; j++)
#pragma unroll
            for (int k = 0; k < 4; k++) acc[i][j][k] = 0.0f;

    auto issue = [&](int buf, int t) {
        int k0 = t * 32;
        uint32_t as = smem_u32(smh + buf * STAGE_H);
        uint32_t bs = as + 128 * LAH * 2;
#pragma unroll
        for (int i = 0; i < 2; i++) {
            int q = tid + i * 256;
            int m = q >> 2, c16 = q & 3;
            cpa16(as + (m * LAH + c16 * 8) * 2,
                  A + (long)(row0 + m) * lda + k0 + c16 * 8);
        }
        {
            int n = tid >> 2, c16 = tid & 3;
            cpa16(bs + (n * LBH + c16 * 8) * 2,
                  Bt + (long)(col0 + n) * ldb + k0 + c16 * 8);
        }
        cp_commit();
    };
    auto compute = [&](int buf) {
        const __half* ab = smh + buf * STAGE_H;
        const __half* bb = ab + 128 * LAH;
#pragma unroll
        for (int ks = 0; ks < 32; ks += 16) {
            uint32_t af[2][4], bf[4][2];
#pragma unroll
            for (int mt = 0; mt < 2; mt++) {
                const __half* p = ab + (wm0 + mt * 16 + gid) * LAH + ks + 2 * tg;
                af[mt][0] = *(const uint32_t*)p;
                af[mt][1] = *(const uint32_t*)(p + 8 * LAH);
                af[mt][2] = *(const uint32_t*)(p + 8);
                af[mt][3] = *(const uint32_t*)(p + 8 * LAH + 8);
            }
#pragma unroll
            for (int nt = 0; nt < 4; nt++) {
                const __half* p = bb + (wn0 + nt * 8 + gid) * LBH + ks + 2 * tg;
                bf[nt][0] = *(const uint32_t*)p;
                bf[nt][1] = *(const uint32_t*)(p + 8);
            }
#pragma unroll
            for (int mt = 0; mt < 2; mt++)
#pragma unroll
                for (int nt = 0; nt < 4; nt++)
                    mma_f16(acc[mt][nt], af[mt], bf[nt]);
        }
    };

    const int TILES = K / 32;                 // >= 8 for all our shapes
    issue(0, 0);
    issue(1, 1);
    issue(2, 2);
    int buf = 0, nxt = 3;
    for (int t = 0; t < TILES; t++) {
        cp_wait<STGH - 2>();
        __syncthreads();
        if (t + STGH - 1 < TILES) issue(nxt, t + STGH - 1);
        else cp_commit();
        compute(buf);
        buf = (buf + 1 == STGH) ? 0 : buf + 1;
        nxt = (nxt + 1 == STGH) ? 0 : nxt + 1;
        __syncthreads();
    }

#pragma unroll
    for (int mt = 0; mt < 2; mt++)
#pragma unroll
        for (int nt = 0; nt < 4; nt++)
#pragma unroll
            for (int half = 0; half < 2; half++) {
                int r = row0 + wm0 + mt * 16 + gid + half * 8;
                int c = col0 + wn0 + nt * 8 + 2 * tg;
                float v0 = acc[mt][nt][half * 2 + 0];
                float v1 = acc[mt][nt][half * 2 + 1];
                if (EPI == 4) {
                    *(__half2*)((__half*)Cv + (long)r * ldc + c) = __floats2half2_rn(v0, v1);
                } else if (EPI == 5) {
                    __half* H = (__half*)Cv;
                    int bb2 = r >> 10, rl = r & 1023;
                    H[((long)bb2 * DIM + c) * NN_ + rl] = __float2half_rn(v0);
                    H[((long)bb2 * DIM + c + 1) * NN_ + rl] = __float2half_rn(v1);
                } else if (EPI == 3) {
                    v0 += bv[c];
                    v1 += bv[c + 1];
                    v0 = 0.5f * v0 * (1.0f + erff(v0 * 0.70710678118654752f));
                    v1 = 0.5f * v1 * (1.0f + erff(v1 * 0.70710678118654752f));
                    *(__half2*)((__half*)Cv + (long)r * ldc + c) = __floats2half2_rn(v0, v1);
                } else {
                    long off = (long)r * ldc + c;
                    if (EPI == 2 || EPI == 6) {
                        float2 e = *(const float2*)(E + off);
                        v0 += e.x + bv[c];
                        v1 += e.y + bv[c + 1];
                    }
                    float2 o; o.x = v0; o.y = v1;
                    *(float2*)((float*)Cv + off) = o;
                    if (EPI == 6) {
                        int bb2 = r >> 10, rl = r & 1023;
                        H2[((long)bb2 * DIM + c) * NN_ + rl] = __float2half_rn(v0);
                        H2[((long)bb2 * DIM + c + 1) * NN_ + rl] = __float2half_rn(v1);
                    }
                }
            }
}

template <int EPI>
__global__ __launch_bounds__(256, 3)
void mma_gemm_h(const __half* __restrict__ A, const __half* __restrict__ Bt,
                void* __restrict__ C, const float* __restrict__ E,
                const float* __restrict__ bv, __half* __restrict__ H2,
                int K, int lda, int ldb, int ldc,
                long Ab, long Bb, long Cb) {
    extern __shared__ __align__(16) __half smh[];
    int z = blockIdx.z;
    A += (long)z * Ab;
    Bt += (long)z * Bb;
    void* Cz = (EPI == 3 || EPI == 4 || EPI == 5)
               ? (void*)((__half*)C + (long)z * Cb)
               : (void*)((float*)C + (long)z * Cb);
    gemm_core_h<EPI>(A, Bt, Cz, E, bv, H2,
                     K, lda, ldb, ldc, blockIdx.y * 128, blockIdx.x * 64, smh);
}

// merged kv + q: bx [0,4) -> K fp16; [4,8) -> V fp16 transposed; [8,12) -> Q fp16
__global__ __launch_bounds__(256, 3)
void kvq_gemm(const __half* __restrict__ xn, const __half* __restrict__ Wkvt,
              const __half* __restrict__ xma, const __half* __restrict__ Wqt) {
    extern __shared__ __align__(16) __half smh[];
    int row0 = blockIdx.y * 128;
    int bx = blockIdx.x;
    if (bx < 4)
        gemm_core_h<4>(xn, Wkvt, (void*)g_kh, nullptr, nullptr, nullptr,
                       DIM, DIM, DIM, DIM, row0, bx * 64, smh);
    else if (bx < 8)
        gemm_core_h<5>(xn, Wkvt + 256 * DIM, (void*)g_vth, nullptr, nullptr, nullptr,
                       DIM, DIM, DIM, 0, row0, (bx - 4) * 64, smh);
    else
        gemm_core_h<4>(xma, Wqt, (void*)g_qh, nullptr, nullptr, nullptr,
                       DIM, DIM, DIM, DIM, row0, (bx - 8) * 64, smh);
}

// ---------------- fused flash attention, fp16 (m16n8k16), bias prefetched to smem ---------
// smem: Q[128][72] + K[2][128*72] + Vt[2][64*136] + Bias[2][128*136]  (halves)
#define FL_SMEM ((128 * 72 + 2 * 128 * 72 + 2 * 64 * 136 + 2 * 128 * 136) * 2)

__global__ __launch_bounds__(256)
void flash_kernel(const __half* __restrict__ Qg, const __half* __restrict__ Kg,
                  const __half* __restrict__ Vtg, const __half* __restrict__ biasg,
                  __half* __restrict__ Og) {
    extern __shared__ __align__(16) __half smh[];
    __half* Qs = smh;
    __half* Ks = Qs + 128 * 72;
    __half* Vts = Ks + 2 * 128 * 72;
    __half* Bs = Vts + 2 * 64 * 136;

    const int i0 = blockIdx.x * 128;
    const int h = blockIdx.y, b = blockIdx.z;
    const __half* Qp = Qg + (long)b * NN_ * DIM + h * DH;
    const __half* Kp = Kg + (long)b * NN_ * DIM + h * DH;
    const __half* Vtp = Vtg + ((long)b * DIM + h * DH) * NN_;
    const __half* Bp = biasg + ((long)(b * HEADS + h)) * NN_ * NN_ + (long)i0 * NN_;

    const int tid = threadIdx.x, wid = tid >> 5, lane = tid & 31;
    const int gid = lane >> 2, tg = lane & 3;
    const int wm0 = wid * 16;

    auto issue_kv = [&](int buf, int j0) {
        uint32_t ks = smem_u32(Ks + buf * 128 * 72);
        uint32_t vs = smem_u32(Vts + buf * 64 * 136);
        uint32_t bsm = smem_u32(Bs + buf * 128 * 136);
#pragma unroll
        for (int t = 0; t < 4; t++) {
            int q = tid + t * 256;
            int n = q >> 3, c8 = q & 7;
            cpa16(ks + (n * 72 + c8 * 8) * 2, Kp + (long)(j0 + n) * DIM + c8 * 8);
        }
#pragma unroll
        for (int t = 0; t < 4; t++) {
            int q = tid + t * 256;
            int r = q >> 4, c16 = q & 15;
            cpa16(vs + (r * 136 + c16 * 8) * 2, Vtp + (long)r * NN_ + j0 + c16 * 8);
        }
#pragma unroll
        for (int t = 0; t < 8; t++) {
            int q = tid + t * 256;
            int r = q >> 4, c16 = q & 15;
            cpa16(bsm + (r * 136 + c16 * 8) * 2, Bp + (long)r * NN_ + j0 + c16 * 8);
        }
        cp_commit();
    };

    issue_kv(0, 0);

#pragma unroll
    for (int t = 0; t < 4; t++) {
        int q = tid + t * 256;
        int m = q >> 3, c8 = q & 7;
        *(uint4*)(Qs + m * 72 + c8 * 8) = *(const uint4*)(Qp + (long)(i0 + m) * DIM + c8 * 8);
    }

    float oacc[8][4];
#pragma unroll
    for (int i = 0; i < 8; i++)
#pragma unroll
        for (int j = 0; j < 4; j++) oacc[i][j] = 0.0f;
    float li0 = 0.0f, li1 = 0.0f;

    for (int t = 0; t < NN_ / 128; t++) {
        const int j0 = t * 128;
        const int buf = t & 1;
        cp_wait<0>();
        __syncthreads();
        if (t + 1 < NN_ / 128) issue_kv(buf ^ 1, j0 + 128);

        const __half* kb = Ks + buf * 128 * 72;
        const __half* vb = Vts + buf * 64 * 136;
        const __half* bsm = Bs + buf * 128 * 136;

        float s[16][4];
#pragma unroll
        for (int i = 0; i < 16; i++)
#pragma unroll
            for (int j = 0; j < 4; j++) s[i][j] = 0.0f;
#pragma unroll
        for (int ks = 0; ks < 64; ks += 16) {
            uint32_t a[4];
            const __half* pa = Qs + (wm0 + gid) * 72 + ks + 2 * tg;
            a[0] = *(const uint32_t*)pa;
            a[1] = *(const uint32_t*)(pa + 8 * 72);
            a[2] = *(const uint32_t*)(pa + 8);
            a[3] = *(const uint32_t*)(pa + 8 * 72 + 8);
#pragma unroll
            for (int nt = 0; nt < 16; nt++) {
                const __half* pb = kb + (nt * 8 + gid) * 72 + ks + 2 * tg;
                uint32_t bf[2] = { *(const uint32_t*)pb, *(const uint32_t*)(pb + 8) };
                mma_f16(s[nt], a, bf);
            }
        }

#pragma unroll
        for (int nt = 0; nt < 16; nt++) {
            const __half* pb0 = bsm + (wm0 + gid) * 136 + nt * 8 + 2 * tg;
            float2 e0 = __half22float2(*(const __half2*)pb0);
            float2 e1 = __half22float2(*(const __half2*)(pb0 + 8 * 136));
            s[nt][0] = __expf(fmaf(s[nt][0], SCALE, e0.x)); li0 += s[nt][0];
            s[nt][1] = __expf(fmaf(s[nt][1], SCALE, e0.y)); li0 += s[nt][1];
            s[nt][2] = __expf(fmaf(s[nt][2], SCALE, e1.x)); li1 += s[nt][2];
            s[nt][3] = __expf(fmaf(s[nt][3], SCALE, e1.y)); li1 += s[nt][3];
        }

#pragma unroll
        for (int ge = 0; ge < 16; ge += 2) {
            uint32_t pa4[4];
            pa4[0] = packh(s[ge][0], s[ge][1]);
            pa4[1] = packh(s[ge][2], s[ge][3]);
            pa4[2] = packh(s[ge + 1][0], s[ge + 1][1]);
            pa4[3] = packh(s[ge + 1][2], s[ge + 1][3]);
            int k0 = ge * 8;
#pragma unroll
            for (int nt = 0; nt < 8; nt++) {
                const __half* pb = vb + (nt * 8 + gid) * 136 + k0 + 2 * tg;
                uint32_t bf[2] = { *(const uint32_t*)pb, *(const uint32_t*)(pb + 8) };
                mma_f16(oacc[nt], pa4, bf);
            }
        }
    }

    li0 += __shfl_xor_sync(0xffffffffu, li0, 1);
    li0 += __shfl_xor_sync(0xffffffffu, li0, 2);
    li1 += __shfl_xor_sync(0xffffffffu, li1, 1);
    li1 += __shfl_xor_sync(0xffffffffu, li1, 2);
    float iv0 = 1.0f / li0, iv1 = 1.0f / li1;
#pragma unroll
    for (int nt = 0; nt < 8; nt++) {
        long off = ((long)b * NN_ + i0 + wm0 + gid) * DIM + h * DH + nt * 8 + 2 * tg;
        *(__half2*)(Og + off) = __floats2half2_rn(oacc[nt][0] * iv0, oacc[nt][1] * iv0);
        *(__half2*)(Og + off + 8 * DIM) = __floats2half2_rn(oacc[nt][2] * iv1, oacc[nt][3] * iv1);
    }
}

// ---------------- merged tiled transpose fp32 -> fp16 (all weights + x_in, one launch) ----
struct TJobs {
    const float* src[7];
    __half* dst[7];
    int K[7], N[7];
    int off[8];
};

__global__ void wtrans_all(TJobs J) {
    __shared__ float tile[32][33];
    int bid = blockIdx.x;
    int j = 0;
    while (bid >= J.off[j + 1]) j++;
    int local = bid - J.off[j];
    int K = J.K[j], N = J.N[j];
    int tn = N >> 5;
    int per_z = tn * (K >> 5);
    int z = local / per_z, rem = local % per_z;
    int n0 = (rem % tn) * 32, k0 = (rem / tn) * 32;
    const float* src = J.src[j] + (long)z * K * N;
    __half* dst = J.dst[j] + (long)z * K * N;
    int tx = threadIdx.x, ty = threadIdx.y;
#pragma unroll
    for (int i = 0; i < 32; i += 8)
        tile[ty + i][tx] = src[(long)(k0 + ty + i) * N + n0 + tx];
    __syncthreads();
#pragma unroll
    for (int i = 0; i < 32; i += 8)
        dst[(long)(n0 + ty + i) * K + k0 + tx] = __float2half_rn(tile[tx][ty + i]);
}

// ---------------- prep: add_attn(fp16) ; G = fp16(softmax(mean(b0)*mean(b1))) ----------
__global__ __launch_bounds__(256)
void prep_kernel(const float* __restrict__ ab) {
    __shared__ float sh[32];
    int b = blockIdx.x >> 10;
    int i = blockIdx.x & 1023;
    const long BHNN = (long)BB * HEADS * NN_ * NN_;
    int tid = threadIdx.x;
    int j4 = tid * 4;
    float4 sa = make_float4(0, 0, 0, 0), sb = make_float4(0, 0, 0, 0);
#pragma unroll
    for (int h = 0; h < HEADS; h++) {
        long o = (((long)(b * HEADS + h) * NN_) + i) * NN_ + j4;
        float4 a0 = *(const float4*)(ab + o);
        float4 a1 = *(const float4*)(ab + BHNN + o);
        sa.x += a0.x; sa.y += a0.y; sa.z += a0.z; sa.w += a0.w;
        sb.x += a1.x; sb.y += a1.y; sb.z += a1.z; sb.w += a1.w;
        union { __half2 h2[2]; uint2 u; } pk;
        pk.h2[0] = __floats2half2_rn(a0.x + a1.x, a0.y + a1.y);
        pk.h2[1] = __floats2half2_rn(a0.z + a1.z, a0.w + a1.w);
        *(uint2*)(&g_bias[o]) = pk.u;
    }
    float val[4];
    val[0] = (sa.x * 0.25f) * (sb.x * 0.25f);
    val[1] = (sa.y * 0.25f) * (sb.y * 0.25f);
    val[2] = (sa.z * 0.25f) * (sb.z * 0.25f);
    val[3] = (sa.w * 0.25f) * (sb.w * 0.25f);
    float m = fmaxf(fmaxf(val[0], val[1]), fmaxf(val[2], val[3]));
    m = block_max(m, sh);
    float s = 0.0f;
#pragma unroll
    for (int t = 0; t < 4; t++) { val[t] = __expf(val[t] - m); s += val[t]; }
    s = block_sum(s, sh);
    float inv = 1.0f / s;
    long rowo = ((long)(b * NN_ + i)) * NN_ + j4;
    union { __half2 h2[2]; uint2 u; } gk;
    gk.h2[0] = __floats2half2_rn(val[0] * inv, val[1] * inv);
    gk.h2[1] = __floats2half2_rn(val[2] * inv, val[3] * inv);
    *(uint2*)(&g_Gh[rowo]) = gk.u;
}

// ---------------- LayerNorm: one warp/row, one-pass; fp16 output ----------------
__device__ __forceinline__ void ln_row(const float* __restrict__ in, __half* __restrict__ out,
                                       const float* __restrict__ g, const float* __restrict__ bt,
                                       long row, int lane, int relu) {
    const float* p = in + row * DIM + lane * 8;
    float4 v0 = *(const float4*)p;
    float4 v1 = *(const float4*)(p + 4);
    float s = v0.x + v0.y + v0.z + v0.w + v1.x + v1.y + v1.z + v1.w;
    float q = v0.x * v0.x + v0.y * v0.y + v0.z * v0.z + v0.w * v0.w
            + v1.x * v1.x + v1.y * v1.y + v1.z * v1.z + v1.w * v1.w;
#pragma unroll
    for (int o = 16; o; o >>= 1) {
        s += __shfl_xor_sync(0xffffffffu, s, o);
        q += __shfl_xor_sync(0xffffffffu, q, o);
    }
    float mean = s * (1.0f / DIM);
    float var = q * (1.0f / DIM) - mean * mean;
    float rstd = rsqrtf(var + EPS);
    const float* gp = g + lane * 8;
    const float* bp = bt + lane * 8;
    float4 g0 = *(const float4*)gp, g1 = *(const float4*)(gp + 4);
    float4 b0 = *(const float4*)bp, b1 = *(const float4*)(bp + 4);
    float o8[8];
    o8[0] = (v0.x - mean) * rstd * g0.x + b0.x; o8[1] = (v0.y - mean) * rstd * g0.y + b0.y;
    o8[2] = (v0.z - mean) * rstd * g0.z + b0.z; o8[3] = (v0.w - mean) * rstd * g0.w + b0.w;
    o8[4] = (v1.x - mean) * rstd * g1.x + b1.x; o8[5] = (v1.y - mean) * rstd * g1.y + b1.y;
    o8[6] = (v1.z - mean) * rstd * g1.z + b1.z; o8[7] = (v1.w - mean) * rstd * g1.w + b1.w;
    if (relu) {
#pragma unroll
        for (int t = 0; t < 8; t++) o8[t] = fmaxf(o8[t], 0.0f);
    }
    union { __half2 h2[4]; uint4 u; } pk;
    pk.h2[0] = __floats2half2_rn(o8[0], o8[1]);
    pk.h2[1] = __floats2half2_rn(o8[2], o8[3]);
    pk.h2[2] = __floats2half2_rn(o8[4], o8[5]);
    pk.h2[3] = __floats2half2_rn(o8[6], o8[7]);
    *(uint4*)(out + row * DIM + lane * 8) = pk.u;
}

__global__ __launch_bounds__(256)
void ln_one(const float* __restrict__ in, __half* __restrict__ out,
            const float* __restrict__ g, const float* __restrict__ bt) {
    int w = threadIdx.x >> 5, lane = threadIdx.x & 31;
    ln_row(in, out, g, bt, (long)blockIdx.x * 8 + w, lane, 0);
}

__global__ __launch_bounds__(256)
void ln_fused(const float* __restrict__ inA, __half* __restrict__ outA,
              const float* __restrict__ gA, const float* __restrict__ bA,
              const float* __restrict__ inB, __half* __restrict__ outB,
              const float* __restrict__ gB, const float* __restrict__ bB, int nA) {
    int w = threadIdx.x >> 5, lane = threadIdx.x & 31;
    int bid = blockIdx.x;
    if (bid < nA)
        ln_row(inA, outA, gA, bA, (long)bid * 8 + w, lane, 1);
    else
        ln_row(inB, outB, gB, bB, (long)(bid - nA) * 8 + w, lane, 0);
}

// ---------------- host ----------------
extern "C" void kernel_launch(void* const* d_in, const int* in_sizes, int n_in,
                              void* d_out, int out_size) {
    const float* x_in   = (const float*)d_in[0];
    const float* abias  = (const float*)d_in[1];
    const float* ln1_g  = (const float*)d_in[2];
    const float* ln1_b  = (const float*)d_in[3];
    const float* Wkv    = (const float*)d_in[4];
    const float* Wq     = (const float*)d_in[5];
    const float* Wo     = (const float*)d_in[6];
    const float* bo     = (const float*)d_in[7];
    const float* ln2_g  = (const float*)d_in[8];
    const float* ln2_b  = (const float*)d_in[9];
    const float* W1     = (const float*)d_in[10];
    const float* b1     = (const float*)d_in[11];
    const float* W2     = (const float*)d_in[12];
    const float* b2     = (const float*)d_in[13];
    const float* Wg     = (const float*)d_in[14];
    const float* lng_g  = (const float*)d_in[15];
    const float* lng_b  = (const float*)d_in[16];
    float* out = (float*)d_out;

    float *px, *pxma;
    __half *pGh, *pbias, *pxnh, *pxmah, *pgxh, *paoh, *pffh, *pxth, *pkh, *pqh, *pvth, *pwh;
    cudaGetSymbolAddress((void**)&px, g_x);
    cudaGetSymbolAddress((void**)&pxma, g_xma);
    cudaGetSymbolAddress((void**)&pGh, g_Gh);
    cudaGetSymbolAddress((void**)&pbias, g_bias);
    cudaGetSymbolAddress((void**)&pxnh, g_xnh);
    cudaGetSymbolAddress((void**)&pxmah, g_xmah);
    cudaGetSymbolAddress((void**)&pgxh, g_gxh);
    cudaGetSymbolAddress((void**)&paoh, g_aoh);
    cudaGetSymbolAddress((void**)&pffh, g_ffh);
    cudaGetSymbolAddress((void**)&pxth, g_xth);
    cudaGetSymbolAddress((void**)&pkh, g_kh);
    cudaGetSymbolAddress((void**)&pqh, g_qh);
    cudaGetSymbolAddress((void**)&pvth, g_vth);
    cudaGetSymbolAddress((void**)&pwh, g_wh);

    const int ROWS = BB * NN_;           // 4096
    const long ND = (long)NN_ * DIM;
    dim3 blk(256);
    dim3 tblk(32, 8);

    cudaFuncSetAttribute(mma_gemm_h<0>, cudaFuncAttributeMaxDynamicSharedMemorySize, SM_GH);
    cudaFuncSetAttribute(mma_gemm_h<2>, cudaFuncAttributeMaxDynamicSharedMemorySize, SM_GH);
    cudaFuncSetAttribute(mma_gemm_h<3>, cudaFuncAttributeMaxDynamicSharedMemorySize, SM_GH);
    cudaFuncSetAttribute(mma_gemm_h<4>, cudaFuncAttributeMaxDynamicSharedMemorySize, SM_GH);
    cudaFuncSetAttribute(mma_gemm_h<6>, cudaFuncAttributeMaxDynamicSharedMemorySize, SM_GH);
    cudaFuncSetAttribute(kvq_gemm, cudaFuncAttributeMaxDynamicSharedMemorySize, SM_GH);
    cudaFuncSetAttribute(flash_kernel, cudaFuncAttributeMaxDynamicSharedMemorySize, FL_SMEM);

    // one merged transpose launch: 6 weight tensors + x_in -> x^T
    TJobs J;
    J.src[0] = Wkv;  J.dst[0] = pwh + OW_KV; J.K[0] = 256;  J.N[0] = 512;   // z=4
    J.src[1] = Wq;   J.dst[1] = pwh + OW_Q;  J.K[1] = 256;  J.N[1] = 256;
    J.src[2] = Wo;   J.dst[2] = pwh + OW_O;  J.K[2] = 256;  J.N[2] = 256;
    J.src[3] = W1;   J.dst[3] = pwh + OW_1;  J.K[3] = 256;  J.N[3] = 1024;
    J.src[4] = W2;   J.dst[4] = pwh + OW_2;  J.K[4] = 1024; J.N[4] = 256;
    J.src[5] = Wg;   J.dst[5] = pwh + OW_G;  J.K[5] = 256;  J.N[5] = 256;
    J.src[6] = x_in; J.dst[6] = pxth;        J.K[6] = 1024; J.N[6] = 256;
    int nz[7] = {DEPTH, DEPTH, DEPTH, DEPTH, DEPTH, 1, BB};
    J.off[0] = 0;
    for (int j = 0; j < 7; j++)
        J.off[j + 1] = J.off[j] + nz[j] * (J.N[j] >> 5) * (J.K[j] >> 5);
    wtrans_all<<<J.off[7], tblk>>>(J);

    prep_kernel<<<BB * NN_, blk>>>(abias);

    for (int l = 0; l < DEPTH; l++) {
        const float* xcur = (l == 0) ? x_in : px;
        // GX = G @ x -> gxh fp16
        mma_gemm_h<4><<<dim3(DIM / 64, NN_ / 128, BB), blk, SM_GH>>>(
            pGh, pxth, pgxh, nullptr, nullptr, nullptr,
            NN_, NN_, NN_, DIM, (long)NN_ * NN_, (long)DIM * NN_, ND);
        // x_ma_pre = GX @ Wg -> g_xma fp32
        mma_gemm_h<0><<<dim3(DIM / 64, ROWS / 128, 1), blk, SM_GH>>>(
            pgxh, pwh + OW_G, pxma, nullptr, nullptr, nullptr,
            DIM, DIM, DIM, DIM, 0, 0, 0);
        // merged: xmah = relu(LN(xma)) ; xnh = LN(x)
        ln_fused<<<ROWS / 4, blk>>>(pxma, pxmah, lng_g, lng_b,
                                    xcur, pxnh, ln1_g + l * DIM, ln1_b + l * DIM, ROWS / 8);
        // merged K/V/Q -> fp16 (V transposed)
        kvq_gemm<<<dim3(12, ROWS / 128, 1), blk, SM_GH>>>(
            pxnh, pwh + OW_KV + (long)l * 512 * DIM,
            pxmah, pwh + OW_Q + (long)l * DIM * DIM);
        // fused fp16 attention -> aoh
        flash_kernel<<<dim3(NN_ / 128, HEADS, BB), blk, FL_SMEM>>>(pqh, pkh, pvth, pbias, paoh);
        // x = x + ao @ Wo[l] + bo[l]
        mma_gemm_h<2><<<dim3(DIM / 64, ROWS / 128, 1), blk, SM_GH>>>(
            paoh, pwh + OW_O + (long)l * DIM * DIM, px, xcur, bo + l * DIM, nullptr,
            DIM, DIM, DIM, DIM, 0, 0, 0);
        // xn2 = LN(x) -> xnh
        ln_one<<<ROWS / 8, blk>>>(px, pxnh, ln2_g + l * DIM, ln2_b + l * DIM);
        // ff = gelu(xn2 @ W1[l] + b1[l]) -> ffh fp16
        mma_gemm_h<3><<<dim3(MLP / 64, ROWS / 128, 1), blk, SM_GH>>>(
            pxnh, pwh + OW_1 + (long)l * MLP * DIM, pffh, nullptr, b1 + l * MLP, nullptr,
            DIM, DIM, DIM, MLP, 0, 0, 0);
        // x = x + ff @ W2[l] + b2[l]; also x^T fp16 for next GX
        if (l == DEPTH - 1) {
            mma_gemm_h<2><<<dim3(DIM / 64, ROWS / 128, 1), blk, SM_GH>>>(
                pffh, pwh + OW_2 + (long)l * DIM * MLP, out, px, b2 + l * DIM, nullptr,
                MLP, MLP, MLP, DIM, 0, 0, 0);
        } else {
            mma_gemm_h<6><<<dim3(DIM / 64, ROWS / 128, 1), blk, SM_GH>>>(
                pffh, pwh + OW_2 + (long)l * DIM * MLP, px, px, b2 + l * DIM, pxth,
                MLP, MLP, MLP, DIM, 0, 0, 0);
        }
    }
}